// round 2
// baseline (speedup 1.0000x reference)
#include <cuda_runtime.h>

#define NB     8
#define NH     16
#define SLQ    2048
#define SLKV   1024
#define DMODEL 1024
#define DIMG   512
#define DHEAD  64

// ---------------- scratch (allocation-free rule: __device__ globals) ----------
__device__ float g_Q[(size_t)NB * SLQ * DMODEL];   // 64 MB  projected Q
__device__ float g_K[(size_t)NB * SLKV * DMODEL];  // 32 MB  projected K
__device__ float g_V[(size_t)NB * SLKV * DMODEL];  // 32 MB  projected V
__device__ float g_A[(size_t)NB * SLQ * DMODEL];   // 64 MB  attention output (concat)

// ============================================================================
// SGEMM + bias: C[M,N] = A[M,K] @ W[K,N] + bias[N]
// 128x128 CTA tile, BK=16, 256 threads, 8x8 microtile (split 4+4 fragments).
// M % 128 == 0, N % 128 == 0, K % 16 == 0 (all shapes here satisfy this).
// ============================================================================
__global__ __launch_bounds__(256)
void sgemm_bias(const float* __restrict__ A, const float* __restrict__ W,
                const float* __restrict__ bias, float* __restrict__ C,
                int M, int N, int K)
{
    __shared__ float As[16][132];   // A tile, transposed [k][m], padded
    __shared__ float Bs[16][132];   // W tile [k][n], padded

    const int tid = threadIdx.x;
    const int tx  = tid & 15;
    const int ty  = tid >> 4;
    const int m0  = blockIdx.y * 128;
    const int n0  = blockIdx.x * 128;

    float acc[8][8];
#pragma unroll
    for (int i = 0; i < 8; ++i)
#pragma unroll
        for (int j = 0; j < 8; ++j) acc[i][j] = 0.0f;

    const int ar = tid >> 2;          // 0..63 (A tile row, +64 second half)
    const int ak = (tid & 3) << 2;    // 0,4,8,12
    const int bk = tid >> 5;          // 0..7  (W tile k row, +8 second half)
    const int bn = (tid & 31) << 2;   // 0..124

    for (int k0 = 0; k0 < K; k0 += 16) {
#pragma unroll
        for (int h = 0; h < 2; ++h) {
            const float4 av =
                *(const float4*)&A[(size_t)(m0 + ar + h * 64) * K + k0 + ak];
            As[ak + 0][ar + h * 64] = av.x;
            As[ak + 1][ar + h * 64] = av.y;
            As[ak + 2][ar + h * 64] = av.z;
            As[ak + 3][ar + h * 64] = av.w;
            *(float4*)&Bs[bk + h * 8][bn] =
                *(const float4*)&W[(size_t)(k0 + bk + h * 8) * N + n0 + bn];
        }
        __syncthreads();

#pragma unroll
        for (int kk = 0; kk < 16; ++kk) {
            float a[8], b[8];
            *(float4*)&a[0] = *(const float4*)&As[kk][ty * 4];
            *(float4*)&a[4] = *(const float4*)&As[kk][64 + ty * 4];
            *(float4*)&b[0] = *(const float4*)&Bs[kk][tx * 4];
            *(float4*)&b[4] = *(const float4*)&Bs[kk][64 + tx * 4];
#pragma unroll
            for (int i = 0; i < 8; ++i)
#pragma unroll
                for (int j = 0; j < 8; ++j)
                    acc[i][j] = fmaf(a[i], b[j], acc[i][j]);
        }
        __syncthreads();
    }

#pragma unroll
    for (int ih = 0; ih < 2; ++ih)
#pragma unroll
        for (int i = 0; i < 4; ++i) {
            const int row = m0 + ih * 64 + ty * 4 + i;
#pragma unroll
            for (int jh = 0; jh < 2; ++jh) {
                const int col = n0 + jh * 64 + tx * 4;
                float4 r;
                r.x = acc[ih * 4 + i][jh * 4 + 0] + bias[col + 0];
                r.y = acc[ih * 4 + i][jh * 4 + 1] + bias[col + 1];
                r.z = acc[ih * 4 + i][jh * 4 + 2] + bias[col + 2];
                r.w = acc[ih * 4 + i][jh * 4 + 3] + bias[col + 3];
                *(float4*)&C[(size_t)row * N + col] = r;
            }
        }
}

// ============================================================================
// Flash attention: one CTA = 64 q-rows of one (b, h).
// 256 threads as 16(tx: kv / d cols) x 16(ty: q rows), 4x4 fragments.
// Online softmax via width-16 shuffles (each 16-lane group owns q rows ty*4..+3,
// so the running max/sum/rescale live entirely in registers).
// smem (dynamic, 68608 B): Qt[64][68] ([d][q], prescaled by 1/8),
//                          Kt[64][68] ([d][kv]), Ps[64][68] ([kv][q]),
//                          Vs[64][64] ([kv][d]).
// ============================================================================
#define ATTN_SMEM_FLOATS (3 * 64 * 68 + 64 * 64)
#define ATTN_SMEM_BYTES  (ATTN_SMEM_FLOATS * 4)

__global__ __launch_bounds__(256)
void attn_kernel()
{
    extern __shared__ float sm[];
    float* Qt = sm;                   // [64][68]
    float* Kt = Qt + 64 * 68;         // [64][68]
    float* Ps = Kt + 64 * 68;         // [64][68]
    float* Vs = Ps + 64 * 68;         // [64][64]

    const int qb  = blockIdx.x;       // 0..31
    const int h   = blockIdx.y;       // 0..15
    const int b   = blockIdx.z;       // 0..7
    const int tid = threadIdx.x;
    const int tx  = tid & 15;
    const int ty  = tid >> 4;

    const float* Qg = g_Q + ((size_t)b * SLQ + qb * 64) * DMODEL + h * DHEAD;
    const float* Kg = g_K + (size_t)b * SLKV * DMODEL + h * DHEAD;
    const float* Vg = g_V + (size_t)b * SLKV * DMODEL + h * DHEAD;

    // Load Q tile transposed, prescaled by 1/sqrt(64)
#pragma unroll
    for (int it = 0; it < 4; ++it) {
        const int idx  = tid + it * 256;
        const int qrow = idx >> 4;
        const int d4   = (idx & 15) << 2;
        const float4 v = *(const float4*)&Qg[(size_t)qrow * DMODEL + d4];
        Qt[(d4 + 0) * 68 + qrow] = v.x * 0.125f;
        Qt[(d4 + 1) * 68 + qrow] = v.y * 0.125f;
        Qt[(d4 + 2) * 68 + qrow] = v.z * 0.125f;
        Qt[(d4 + 3) * 68 + qrow] = v.w * 0.125f;
    }

    float m[4], l[4], o[4][4];
#pragma unroll
    for (int i = 0; i < 4; ++i) {
        m[i] = -3.0e38f; l[i] = 0.0f;
#pragma unroll
        for (int j = 0; j < 4; ++j) o[i][j] = 0.0f;
    }

    for (int kv0 = 0; kv0 < SLKV; kv0 += 64) {
        __syncthreads();  // previous tile's PV readers done before overwrite
#pragma unroll
        for (int it = 0; it < 4; ++it) {
            const int idx = tid + it * 256;
            const int r   = idx >> 4;
            const int d4  = (idx & 15) << 2;
            const float4 kvv = *(const float4*)&Kg[(size_t)(kv0 + r) * DMODEL + d4];
            Kt[(d4 + 0) * 68 + r] = kvv.x;
            Kt[(d4 + 1) * 68 + r] = kvv.y;
            Kt[(d4 + 2) * 68 + r] = kvv.z;
            Kt[(d4 + 3) * 68 + r] = kvv.w;
            *(float4*)&Vs[r * 64 + d4] =
                *(const float4*)&Vg[(size_t)(kv0 + r) * DMODEL + d4];
        }
        __syncthreads();

        // S = (Q/8) @ K^T : 4x4 fragment, q rows ty*4.., kv cols tx*4..
        float s[4][4];
#pragma unroll
        for (int i = 0; i < 4; ++i)
#pragma unroll
            for (int j = 0; j < 4; ++j) s[i][j] = 0.0f;

#pragma unroll 16
        for (int d = 0; d < DHEAD; ++d) {
            float a[4], bb[4];
            *(float4*)&a[0]  = *(const float4*)&Qt[d * 68 + ty * 4];
            *(float4*)&bb[0] = *(const float4*)&Kt[d * 68 + tx * 4];
#pragma unroll
            for (int i = 0; i < 4; ++i)
#pragma unroll
                for (int j = 0; j < 4; ++j)
                    s[i][j] = fmaf(a[i], bb[j], s[i][j]);
        }

        // Online softmax per q row (reduce across the 16 tx lanes)
#pragma unroll
        for (int i = 0; i < 4; ++i) {
            float tm = fmaxf(fmaxf(s[i][0], s[i][1]), fmaxf(s[i][2], s[i][3]));
#pragma unroll
            for (int off = 8; off >= 1; off >>= 1)
                tm = fmaxf(tm, __shfl_xor_sync(0xffffffffu, tm, off, 16));
            const float mn    = fmaxf(m[i], tm);
            const float alpha = __expf(m[i] - mn);
            m[i] = mn;
            float rs = 0.0f;
#pragma unroll
            for (int j = 0; j < 4; ++j) {
                s[i][j] = __expf(s[i][j] - mn);
                rs += s[i][j];
            }
#pragma unroll
            for (int off = 8; off >= 1; off >>= 1)
                rs += __shfl_xor_sync(0xffffffffu, rs, off, 16);
            l[i] = l[i] * alpha + rs;
#pragma unroll
            for (int j = 0; j < 4; ++j) o[i][j] *= alpha;
            // store P transposed: Ps[kv][q]
#pragma unroll
            for (int j = 0; j < 4; ++j)
                Ps[(tx * 4 + j) * 68 + ty * 4 + i] = s[i][j];
        }
        __syncthreads();

        // O += P @ V : q rows ty*4.., d cols tx*4..
#pragma unroll 16
        for (int kv = 0; kv < 64; ++kv) {
            float a[4], vv[4];
            *(float4*)&a[0]  = *(const float4*)&Ps[kv * 68 + ty * 4];
            *(float4*)&vv[0] = *(const float4*)&Vs[kv * 64 + tx * 4];
#pragma unroll
            for (int i = 0; i < 4; ++i)
#pragma unroll
                for (int j = 0; j < 4; ++j)
                    o[i][j] = fmaf(a[i], vv[j], o[i][j]);
        }
    }

    // finalize: divide by l, write to concat layout g_A[b][q][h*64+d]
#pragma unroll
    for (int i = 0; i < 4; ++i) {
        const float inv = 1.0f / l[i];
        float4 r;
        r.x = o[i][0] * inv;
        r.y = o[i][1] * inv;
        r.z = o[i][2] * inv;
        r.w = o[i][3] * inv;
        *(float4*)&g_A[((size_t)b * SLQ + qb * 64 + ty * 4 + i) * DMODEL +
                       h * DHEAD + tx * 4] = r;
    }
}

// ============================================================================
// kernel_launch: 5 in-stream kernels (graph-capturable, allocation-free)
// Inputs (metadata order): q, k, v, Wq, bq, Wk, bk, Wv, bv, Wo, bo
// ============================================================================
extern "C" void kernel_launch(void* const* d_in, const int* in_sizes, int n_in,
                              void* d_out, int out_size)
{
    const float* q  = (const float*)d_in[0];
    const float* k  = (const float*)d_in[1];
    const float* v  = (const float*)d_in[2];
    const float* Wq = (const float*)d_in[3];
    const float* bq = (const float*)d_in[4];
    const float* Wk = (const float*)d_in[5];
    const float* bk = (const float*)d_in[6];
    const float* Wv = (const float*)d_in[7];
    const float* bv = (const float*)d_in[8];
    const float* Wo = (const float*)d_in[9];
    const float* bo = (const float*)d_in[10];
    float* out = (float*)d_out;

    float *gQ, *gK, *gV, *gA;
    cudaGetSymbolAddress((void**)&gQ, g_Q);
    cudaGetSymbolAddress((void**)&gK, g_K);
    cudaGetSymbolAddress((void**)&gV, g_V);
    cudaGetSymbolAddress((void**)&gA, g_A);

    cudaFuncSetAttribute(attn_kernel,
                         cudaFuncAttributeMaxDynamicSharedMemorySize,
                         ATTN_SMEM_BYTES);

    // Q = q @ Wq + bq           [16384 x 1024] x [1024 x 1024]
    sgemm_bias<<<dim3(DMODEL / 128, NB * SLQ / 128), 256>>>(
        q, Wq, bq, gQ, NB * SLQ, DMODEL, DMODEL);
    // K = k @ Wk + bk           [8192 x 512] x [512 x 1024]
    sgemm_bias<<<dim3(DMODEL / 128, NB * SLKV / 128), 256>>>(
        k, Wk, bk, gK, NB * SLKV, DMODEL, DIMG);
    // V = v @ Wv + bv
    sgemm_bias<<<dim3(DMODEL / 128, NB * SLKV / 128), 256>>>(
        v, Wv, bv, gV, NB * SLKV, DMODEL, DIMG);
    // attention -> g_A
    attn_kernel<<<dim3(SLQ / 64, NH, NB), 256, ATTN_SMEM_BYTES>>>();
    // out = g_A @ Wo + bo
    sgemm_bias<<<dim3(DMODEL / 128, NB * SLQ / 128), 256>>>(
        gA, Wo, bo, out, NB * SLQ, DMODEL, DMODEL);
}

// round 6
// speedup vs baseline: 1.1663x; 1.1663x over previous
#include <cuda_runtime.h>
#include <cuda_bf16.h>
#include <cstdint>
#include <cstddef>

#define NB     8
#define NH     16
#define SLQ    2048
#define SLKV   1024
#define DMODEL 1024
#define DIMG   512
#define DHEAD  64

// ---------------- scratch (allocation-free rule: __device__ globals) ----------
__device__ float g_Q[(size_t)NB * SLQ * DMODEL];
__device__ float g_K[(size_t)NB * SLKV * DMODEL];
__device__ float g_V[(size_t)NB * SLKV * DMODEL];
__device__ float g_A[(size_t)NB * SLQ * DMODEL];

// 3-segment split operands: A3 = [hi | hi | lo], W3t = [hi | lo | hi]
// product = ah*wh + ah*wl + al*wh  (residual al*wl ~ 2^-18)
__device__ __align__(128) __nv_bfloat16 sp_q[(size_t)NB * SLQ  * 3 * DMODEL];
__device__ __align__(128) __nv_bfloat16 sp_k[(size_t)NB * SLKV * 3 * DIMG];
__device__ __align__(128) __nv_bfloat16 sp_v[(size_t)NB * SLKV * 3 * DIMG];
__device__ __align__(128) __nv_bfloat16 sp_a[(size_t)NB * SLQ  * 3 * DMODEL];
__device__ __align__(128) __nv_bfloat16 tw_q[(size_t)DMODEL * 3 * DMODEL];
__device__ __align__(128) __nv_bfloat16 tw_k[(size_t)DMODEL * 3 * DIMG];
__device__ __align__(128) __nv_bfloat16 tw_v[(size_t)DMODEL * 3 * DIMG];
__device__ __align__(128) __nv_bfloat16 tw_o[(size_t)DMODEL * 3 * DMODEL];

// ============================================================================
// low-level helpers (compute_103-safe: cp.async + ldmatrix + mma.sync only)
// ============================================================================
__device__ __forceinline__ uint32_t smem_u32(const void* p) {
    return (uint32_t)__cvta_generic_to_shared(p);
}
__device__ __forceinline__ void cpa16(uint32_t s, const void* g) {
    asm volatile("cp.async.cg.shared.global [%0], [%1], 16;" :: "r"(s), "l"(g));
}
__device__ __forceinline__ void cpa_commit() {
    asm volatile("cp.async.commit_group;" ::: "memory");
}
__device__ __forceinline__ void cpa_wait1() {
    asm volatile("cp.async.wait_group 1;" ::: "memory");
}
__device__ __forceinline__ void ldmx4(uint32_t* r, uint32_t addr) {
    asm volatile("ldmatrix.sync.aligned.m8n8.x4.shared.b16 {%0,%1,%2,%3}, [%4];"
                 : "=r"(r[0]), "=r"(r[1]), "=r"(r[2]), "=r"(r[3]) : "r"(addr));
}
__device__ __forceinline__ void mma16816(float* c, const uint32_t* a, const uint32_t* b) {
    asm volatile("mma.sync.aligned.m16n8k16.row.col.f32.bf16.bf16.f32 "
                 "{%0,%1,%2,%3}, {%4,%5,%6,%7}, {%8,%9}, {%0,%1,%2,%3};"
                 : "+f"(c[0]), "+f"(c[1]), "+f"(c[2]), "+f"(c[3])
                 : "r"(a[0]), "r"(a[1]), "r"(a[2]), "r"(a[3]),
                   "r"(b[0]), "r"(b[1]));
}

// ============================================================================
// bf16 mma.sync GEMM: C[M,1024] = A3[M,K3] @ B3t[1024,K3]^T + bias
// 128x128 CTA tile, BK=32, 256 threads (8 warps, 2x4, 64x32 each),
// cp.async double buffer, fp32 accumulate.
// ============================================================================
#define BK   32
#define LDT  40                      // 32 + 8 bf16 pad -> conflict-free ldmatrix

__global__ __launch_bounds__(256, 1)
void gemm_mma(const __nv_bfloat16* __restrict__ A,
              const __nv_bfloat16* __restrict__ B,
              const float* __restrict__ bias,
              float* __restrict__ C, int K2)
{
    __shared__ __nv_bfloat16 As[2][128 * LDT];
    __shared__ __nv_bfloat16 Bs[2][128 * LDT];

    const int tid  = threadIdx.x;
    const int wid  = tid >> 5;
    const int lane = tid & 31;
    const int wm   = (wid >> 2) * 64;      // 0, 64
    const int wn   = (wid & 3) * 32;       // 0..96
    const int m0   = blockIdx.y * 128;
    const int n0   = blockIdx.x * 128;
    const int nIter = K2 / BK;

    const int lr = tid >> 2;               // 0..63
    const int kc = (tid & 3) << 3;         // 0,8,16,24

    float acc[4][4][4];
#pragma unroll
    for (int mi = 0; mi < 4; ++mi)
#pragma unroll
        for (int ni = 0; ni < 4; ++ni)
#pragma unroll
            for (int e = 0; e < 4; ++e) acc[mi][ni][e] = 0.0f;

#define LOAD_STAGE(s, kk)                                                      \
    {                                                                          \
        _Pragma("unroll")                                                      \
        for (int i = 0; i < 2; ++i) {                                          \
            const int row = lr + i * 64;                                       \
            cpa16(smem_u32(&As[s][row * LDT + kc]),                            \
                  &A[(size_t)(m0 + row) * K2 + (kk) + kc]);                    \
            cpa16(smem_u32(&Bs[s][row * LDT + kc]),                            \
                  &B[(size_t)(n0 + row) * K2 + (kk) + kc]);                    \
        }                                                                      \
    }

    LOAD_STAGE(0, 0);
    cpa_commit();

    for (int it = 0; it < nIter; ++it) {
        if (it + 1 < nIter) LOAD_STAGE((it + 1) & 1, (it + 1) * BK);
        cpa_commit();
        cpa_wait1();
        __syncthreads();

        const int s = it & 1;
#pragma unroll
        for (int ks = 0; ks < 2; ++ks) {
            uint32_t af[4][4], bf[2][4];
#pragma unroll
            for (int mi = 0; mi < 4; ++mi)
                ldmx4(af[mi], smem_u32(&As[s][(wm + mi * 16 + (lane & 15)) * LDT +
                                              ks * 16 + (lane >> 4) * 8]));
#pragma unroll
            for (int np = 0; np < 2; ++np)
                ldmx4(bf[np], smem_u32(&Bs[s][(wn + np * 16 + ((lane >> 4) & 1) * 8 +
                                               (lane & 7)) * LDT +
                                              ks * 16 + ((lane >> 3) & 1) * 8]));
#pragma unroll
            for (int mi = 0; mi < 4; ++mi)
#pragma unroll
                for (int ni = 0; ni < 4; ++ni)
                    mma16816(acc[mi][ni], af[mi], &bf[ni >> 1][(ni & 1) * 2]);
        }
        __syncthreads();
    }

    // epilogue: c0,c1 -> (row, col..col+1); c2,c3 -> (row+8, ...)
#pragma unroll
    for (int mi = 0; mi < 4; ++mi) {
        const int row = m0 + wm + mi * 16 + (lane >> 2);
#pragma unroll
        for (int ni = 0; ni < 4; ++ni) {
            const int col = n0 + wn + ni * 8 + (lane & 3) * 2;
            const float bx = __ldg(&bias[col]), by = __ldg(&bias[col + 1]);
            float2 r0 = {acc[mi][ni][0] + bx, acc[mi][ni][1] + by};
            float2 r1 = {acc[mi][ni][2] + bx, acc[mi][ni][3] + by};
            *(float2*)&C[(size_t)row * DMODEL + col]       = r0;
            *(float2*)&C[(size_t)(row + 8) * DMODEL + col] = r1;
        }
    }
#undef LOAD_STAGE
}

// ============================================================================
// converters: fp32 -> 3-segment split bf16
// ============================================================================
__global__ __launch_bounds__(256)
void split3_rows(const float* __restrict__ X, __nv_bfloat16* __restrict__ O,
                 int kshift)
{
    const int K = 1 << kshift;
    const size_t i4 = ((size_t)blockIdx.x * blockDim.x + threadIdx.x) << 2;
    const size_t row = i4 >> kshift;
    const int col = (int)(i4 & (size_t)(K - 1));
    const float4 v = *(const float4*)&X[i4];
    __nv_bfloat16 h[4], l[4];
    h[0] = __float2bfloat16_rn(v.x); l[0] = __float2bfloat16_rn(v.x - __bfloat162float(h[0]));
    h[1] = __float2bfloat16_rn(v.y); l[1] = __float2bfloat16_rn(v.y - __bfloat162float(h[1]));
    h[2] = __float2bfloat16_rn(v.z); l[2] = __float2bfloat16_rn(v.z - __bfloat162float(h[2]));
    h[3] = __float2bfloat16_rn(v.w); l[3] = __float2bfloat16_rn(v.w - __bfloat162float(h[3]));
    __nv_bfloat16* out = O + row * (size_t)(3 * K);
    *(uint2*)&out[col]         = *(const uint2*)h;   // seg0: hi
    *(uint2*)&out[K + col]     = *(const uint2*)h;   // seg1: hi
    *(uint2*)&out[2 * K + col] = *(const uint2*)l;   // seg2: lo
}

__global__ void splitT3(const float* __restrict__ W, __nv_bfloat16* __restrict__ O,
                        int K, int N)
{
    __shared__ float t[32][33];
    const int n0 = blockIdx.x * 32, k0 = blockIdx.y * 32;
    const int tx = threadIdx.x, ty = threadIdx.y;   // (32, 8)
#pragma unroll
    for (int r = 0; r < 4; ++r)
        t[ty + 8 * r][tx] = W[(size_t)(k0 + ty + 8 * r) * N + n0 + tx];
    __syncthreads();
#pragma unroll
    for (int r = 0; r < 4; ++r) {
        const int n = n0 + ty + 8 * r, k = k0 + tx;
        const float v = t[tx][ty + 8 * r];
        const __nv_bfloat16 hi = __float2bfloat16_rn(v);
        const __nv_bfloat16 lo = __float2bfloat16_rn(v - __bfloat162float(hi));
        __nv_bfloat16* o = O + (size_t)n * 3 * K;
        o[k]         = hi;   // seg0: hi
        o[K + k]     = lo;   // seg1: lo
        o[2 * K + k] = hi;   // seg2: hi
    }
}

// ============================================================================
// Flash attention (unchanged — verified correct in round 2)
// ============================================================================
#define ATTN_SMEM_FLOATS (3 * 64 * 68 + 64 * 64)
#define ATTN_SMEM_BYTES  (ATTN_SMEM_FLOATS * 4)

__global__ __launch_bounds__(256)
void attn_kernel()
{
    extern __shared__ float sm[];
    float* Qt = sm;
    float* Kt = Qt + 64 * 68;
    float* Ps = Kt + 64 * 68;
    float* Vs = Ps + 64 * 68;

    const int qb  = blockIdx.x;
    const int h   = blockIdx.y;
    const int b   = blockIdx.z;
    const int tid = threadIdx.x;
    const int tx  = tid & 15;
    const int ty  = tid >> 4;

    const float* Qg = g_Q + ((size_t)b * SLQ + qb * 64) * DMODEL + h * DHEAD;
    const float* Kg = g_K + (size_t)b * SLKV * DMODEL + h * DHEAD;
    const float* Vg = g_V + (size_t)b * SLKV * DMODEL + h * DHEAD;

#pragma unroll
    for (int it = 0; it < 4; ++it) {
        const int idx  = tid + it * 256;
        const int qrow = idx >> 4;
        const int d4   = (idx & 15) << 2;
        const float4 v = *(const float4*)&Qg[(size_t)qrow * DMODEL + d4];
        Qt[(d4 + 0) * 68 + qrow] = v.x * 0.125f;
        Qt[(d4 + 1) * 68 + qrow] = v.y * 0.125f;
        Qt[(d4 + 2) * 68 + qrow] = v.z * 0.125f;
        Qt[(d4 + 3) * 68 + qrow] = v.w * 0.125f;
    }

    float m[4], l[4], o[4][4];
#pragma unroll
    for (int i = 0; i < 4; ++i) {
        m[i] = -3.0e38f; l[i] = 0.0f;
#pragma unroll
        for (int j = 0; j < 4; ++j) o[i][j] = 0.0f;
    }

    for (int kv0 = 0; kv0 < SLKV; kv0 += 64) {
        __syncthreads();
#pragma unroll
        for (int it = 0; it < 4; ++it) {
            const int idx = tid + it * 256;
            const int r   = idx >> 4;
            const int d4  = (idx & 15) << 2;
            const float4 kvv = *(const float4*)&Kg[(size_t)(kv0 + r) * DMODEL + d4];
            Kt[(d4 + 0) * 68 + r] = kvv.x;
            Kt[(d4 + 1) * 68 + r] = kvv.y;
            Kt[(d4 + 2) * 68 + r] = kvv.z;
            Kt[(d4 + 3) * 68 + r] = kvv.w;
            *(float4*)&Vs[r * 64 + d4] =
                *(const float4*)&Vg[(size_t)(kv0 + r) * DMODEL + d4];
        }
        __syncthreads();

        float s[4][4];
#pragma unroll
        for (int i = 0; i < 4; ++i)
#pragma unroll
            for (int j = 0; j < 4; ++j) s[i][j] = 0.0f;

#pragma unroll 16
        for (int d = 0; d < DHEAD; ++d) {
            float a[4], bb[4];
            *(float4*)&a[0]  = *(const float4*)&Qt[d * 68 + ty * 4];
            *(float4*)&bb[0] = *(const float4*)&Kt[d * 68 + tx * 4];
#pragma unroll
            for (int i = 0; i < 4; ++i)
#pragma unroll
                for (int j = 0; j < 4; ++j)
                    s[i][j] = fmaf(a[i], bb[j], s[i][j]);
        }

#pragma unroll
        for (int i = 0; i < 4; ++i) {
            float tm = fmaxf(fmaxf(s[i][0], s[i][1]), fmaxf(s[i][2], s[i][3]));
#pragma unroll
            for (int off = 8; off >= 1; off >>= 1)
                tm = fmaxf(tm, __shfl_xor_sync(0xffffffffu, tm, off, 16));
            const float mn    = fmaxf(m[i], tm);
            const float alpha = __expf(m[i] - mn);
            m[i] = mn;
            float rs = 0.0f;
#pragma unroll
            for (int j = 0; j < 4; ++j) {
                s[i][j] = __expf(s[i][j] - mn);
                rs += s[i][j];
            }
#pragma unroll
            for (int off = 8; off >= 1; off >>= 1)
                rs += __shfl_xor_sync(0xffffffffu, rs, off, 16);
            l[i] = l[i] * alpha + rs;
#pragma unroll
            for (int j = 0; j < 4; ++j) o[i][j] *= alpha;
#pragma unroll
            for (int j = 0; j < 4; ++j)
                Ps[(tx * 4 + j) * 68 + ty * 4 + i] = s[i][j];
        }
        __syncthreads();

#pragma unroll 16
        for (int kv = 0; kv < 64; ++kv) {
            float a[4], vv[4];
            *(float4*)&a[0]  = *(const float4*)&Ps[kv * 68 + ty * 4];
            *(float4*)&vv[0] = *(const float4*)&Vs[kv * 64 + tx * 4];
#pragma unroll
            for (int i = 0; i < 4; ++i)
#pragma unroll
                for (int j = 0; j < 4; ++j)
                    o[i][j] = fmaf(a[i], vv[j], o[i][j]);
        }
    }

#pragma unroll
    for (int i = 0; i < 4; ++i) {
        const float inv = 1.0f / l[i];
        float4 r;
        r.x = o[i][0] * inv;
        r.y = o[i][1] * inv;
        r.z = o[i][2] * inv;
        r.w = o[i][3] * inv;
        *(float4*)&g_A[((size_t)b * SLQ + qb * 64 + ty * 4 + i) * DMODEL +
                       h * DHEAD + tx * 4] = r;
    }
}

// ============================================================================
// host side
// ============================================================================
extern "C" void kernel_launch(void* const* d_in, const int* in_sizes, int n_in,
                              void* d_out, int out_size)
{
    const float* q  = (const float*)d_in[0];
    const float* k  = (const float*)d_in[1];
    const float* v  = (const float*)d_in[2];
    const float* Wq = (const float*)d_in[3];
    const float* bq = (const float*)d_in[4];
    const float* Wk = (const float*)d_in[5];
    const float* bk = (const float*)d_in[6];
    const float* Wv = (const float*)d_in[7];
    const float* bv = (const float*)d_in[8];
    const float* Wo = (const float*)d_in[9];
    const float* bo = (const float*)d_in[10];
    float* out = (float*)d_out;

    float *gQ, *gK, *gV, *gA;
    cudaGetSymbolAddress((void**)&gQ, g_Q);
    cudaGetSymbolAddress((void**)&gK, g_K);
    cudaGetSymbolAddress((void**)&gV, g_V);
    cudaGetSymbolAddress((void**)&gA, g_A);
    __nv_bfloat16 *pq, *pk, *pv, *pa, *pwq, *pwk, *pwv, *pwo;
    cudaGetSymbolAddress((void**)&pq,  sp_q);
    cudaGetSymbolAddress((void**)&pk,  sp_k);
    cudaGetSymbolAddress((void**)&pv,  sp_v);
    cudaGetSymbolAddress((void**)&pa,  sp_a);
    cudaGetSymbolAddress((void**)&pwq, tw_q);
    cudaGetSymbolAddress((void**)&pwk, tw_k);
    cudaGetSymbolAddress((void**)&pwv, tw_v);
    cudaGetSymbolAddress((void**)&pwo, tw_o);

    cudaFuncSetAttribute(attn_kernel, cudaFuncAttributeMaxDynamicSharedMemorySize,
                         ATTN_SMEM_BYTES);

    // 1) split inputs + weights into 3-segment bf16
    split3_rows<<<(NB * SLQ * DMODEL) / 1024, 256>>>(q, pq, 10);
    split3_rows<<<(NB * SLKV * DIMG) / 1024, 256>>>(k, pk, 9);
    split3_rows<<<(NB * SLKV * DIMG) / 1024, 256>>>(v, pv, 9);
    splitT3<<<dim3(DMODEL / 32, DMODEL / 32), dim3(32, 8)>>>(Wq, pwq, DMODEL, DMODEL);
    splitT3<<<dim3(DMODEL / 32, DIMG / 32),   dim3(32, 8)>>>(Wk, pwk, DIMG, DMODEL);
    splitT3<<<dim3(DMODEL / 32, DIMG / 32),   dim3(32, 8)>>>(Wv, pwv, DIMG, DMODEL);
    splitT3<<<dim3(DMODEL / 32, DMODEL / 32), dim3(32, 8)>>>(Wo, pwo, DMODEL, DMODEL);

    // 2) projections on HMMA tensor cores (K' = 3K)
    gemm_mma<<<dim3(DMODEL / 128, NB * SLQ / 128), 256>>>(pq, pwq, bq, gQ, 3 * DMODEL);
    gemm_mma<<<dim3(DMODEL / 128, NB * SLKV / 128), 256>>>(pk, pwk, bk, gK, 3 * DIMG);
    gemm_mma<<<dim3(DMODEL / 128, NB * SLKV / 128), 256>>>(pv, pwv, bv, gV, 3 * DIMG);

    // 3) attention
    attn_kernel<<<dim3(SLQ / 64, NH, NB), 256, ATTN_SMEM_BYTES>>>();

    // 4) output projection
    split3_rows<<<(NB * SLQ * DMODEL) / 1024, 256>>>(gA, pa, 10);
    gemm_mma<<<dim3(DMODEL / 128, NB * SLQ / 128), 256>>>(pa, pwo, bo, out, 3 * DMODEL);
}

// round 7
// speedup vs baseline: 1.9040x; 1.6324x over previous
#include <cuda_runtime.h>
#include <cuda_bf16.h>
#include <cstdint>
#include <cstddef>

#define NB     8
#define NH     16
#define SLQ    2048
#define SLKV   1024
#define DMODEL 1024
#define DIMG   512
#define DHEAD  64

// ---------------- scratch (allocation-free rule: __device__ globals) ----------
__device__ float g_Q[(size_t)NB * SLQ * DMODEL];
__device__ float g_K[(size_t)NB * SLKV * DMODEL];
__device__ float g_V[(size_t)NB * SLKV * DMODEL];

// 3-segment split operands: A3 = [hi | hi | lo], W3t = [hi | lo | hi]
__device__ __align__(128) __nv_bfloat16 sp_q[(size_t)NB * SLQ  * 3 * DMODEL];
__device__ __align__(128) __nv_bfloat16 sp_k[(size_t)NB * SLKV * 3 * DIMG];
__device__ __align__(128) __nv_bfloat16 sp_v[(size_t)NB * SLKV * 3 * DIMG];
__device__ __align__(128) __nv_bfloat16 sp_a[(size_t)NB * SLQ  * 3 * DMODEL];
__device__ __align__(128) __nv_bfloat16 tw_q[(size_t)DMODEL * 3 * DMODEL];
__device__ __align__(128) __nv_bfloat16 tw_k[(size_t)DMODEL * 3 * DIMG];
__device__ __align__(128) __nv_bfloat16 tw_v[(size_t)DMODEL * 3 * DIMG];
__device__ __align__(128) __nv_bfloat16 tw_o[(size_t)DMODEL * 3 * DMODEL];

// ============================================================================
// low-level helpers (compute_103-safe)
// ============================================================================
__device__ __forceinline__ uint32_t smem_u32(const void* p) {
    return (uint32_t)__cvta_generic_to_shared(p);
}
__device__ __forceinline__ void cpa16(uint32_t s, const void* g) {
    asm volatile("cp.async.cg.shared.global [%0], [%1], 16;" :: "r"(s), "l"(g));
}
__device__ __forceinline__ void cpa_commit() {
    asm volatile("cp.async.commit_group;" ::: "memory");
}
__device__ __forceinline__ void cpa_wait1() {
    asm volatile("cp.async.wait_group 1;" ::: "memory");
}
__device__ __forceinline__ void ldmx4(uint32_t* r, uint32_t addr) {
    asm volatile("ldmatrix.sync.aligned.m8n8.x4.shared.b16 {%0,%1,%2,%3}, [%4];"
                 : "=r"(r[0]), "=r"(r[1]), "=r"(r[2]), "=r"(r[3]) : "r"(addr));
}
__device__ __forceinline__ void mma16816(float* c, const uint32_t* a, const uint32_t* b) {
    asm volatile("mma.sync.aligned.m16n8k16.row.col.f32.bf16.bf16.f32 "
                 "{%0,%1,%2,%3}, {%4,%5,%6,%7}, {%8,%9}, {%0,%1,%2,%3};"
                 : "+f"(c[0]), "+f"(c[1]), "+f"(c[2]), "+f"(c[3])
                 : "r"(a[0]), "r"(a[1]), "r"(a[2]), "r"(a[3]),
                   "r"(b[0]), "r"(b[1]));
}
__device__ __forceinline__ uint32_t pack_hi(float x, float y, float& lx, float& ly) {
    __nv_bfloat162 h;
    h.x = __float2bfloat16_rn(x);
    h.y = __float2bfloat16_rn(y);
    lx = x - __bfloat162float(h.x);
    ly = y - __bfloat162float(h.y);
    return *(uint32_t*)&h;
}
__device__ __forceinline__ uint32_t pack2(float x, float y) {
    __nv_bfloat162 h;
    h.x = __float2bfloat16_rn(x);
    h.y = __float2bfloat16_rn(y);
    return *(uint32_t*)&h;
}

// ============================================================================
// bf16 mma.sync GEMM (unchanged from round 6 — verified)
// ============================================================================
#define BK   32
#define LDT  40

__global__ __launch_bounds__(256, 1)
void gemm_mma(const __nv_bfloat16* __restrict__ A,
              const __nv_bfloat16* __restrict__ B,
              const float* __restrict__ bias,
              float* __restrict__ C, int K2)
{
    __shared__ __nv_bfloat16 As[2][128 * LDT];
    __shared__ __nv_bfloat16 Bs[2][128 * LDT];

    const int tid  = threadIdx.x;
    const int wid  = tid >> 5;
    const int lane = tid & 31;
    const int wm   = (wid >> 2) * 64;
    const int wn   = (wid & 3) * 32;
    const int m0   = blockIdx.y * 128;
    const int n0   = blockIdx.x * 128;
    const int nIter = K2 / BK;

    const int lr = tid >> 2;
    const int kc = (tid & 3) << 3;

    float acc[4][4][4];
#pragma unroll
    for (int mi = 0; mi < 4; ++mi)
#pragma unroll
        for (int ni = 0; ni < 4; ++ni)
#pragma unroll
            for (int e = 0; e < 4; ++e) acc[mi][ni][e] = 0.0f;

#define LOAD_STAGE(s, kk)                                                      \
    {                                                                          \
        _Pragma("unroll")                                                      \
        for (int i = 0; i < 2; ++i) {                                          \
            const int row = lr + i * 64;                                       \
            cpa16(smem_u32(&As[s][row * LDT + kc]),                            \
                  &A[(size_t)(m0 + row) * K2 + (kk) + kc]);                    \
            cpa16(smem_u32(&Bs[s][row * LDT + kc]),                            \
                  &B[(size_t)(n0 + row) * K2 + (kk) + kc]);                    \
        }                                                                      \
    }

    LOAD_STAGE(0, 0);
    cpa_commit();

    for (int it = 0; it < nIter; ++it) {
        if (it + 1 < nIter) LOAD_STAGE((it + 1) & 1, (it + 1) * BK);
        cpa_commit();
        cpa_wait1();
        __syncthreads();

        const int s = it & 1;
#pragma unroll
        for (int ks = 0; ks < 2; ++ks) {
            uint32_t af[4][4], bf[2][4];
#pragma unroll
            for (int mi = 0; mi < 4; ++mi)
                ldmx4(af[mi], smem_u32(&As[s][(wm + mi * 16 + (lane & 15)) * LDT +
                                              ks * 16 + (lane >> 4) * 8]));
#pragma unroll
            for (int np = 0; np < 2; ++np)
                ldmx4(bf[np], smem_u32(&Bs[s][(wn + np * 16 + ((lane >> 4) & 1) * 8 +
                                               (lane & 7)) * LDT +
                                              ks * 16 + ((lane >> 3) & 1) * 8]));
#pragma unroll
            for (int mi = 0; mi < 4; ++mi)
#pragma unroll
                for (int ni = 0; ni < 4; ++ni)
                    mma16816(acc[mi][ni], af[mi], &bf[ni >> 1][(ni & 1) * 2]);
        }
        __syncthreads();
    }

#pragma unroll
    for (int mi = 0; mi < 4; ++mi) {
        const int row = m0 + wm + mi * 16 + (lane >> 2);
#pragma unroll
        for (int ni = 0; ni < 4; ++ni) {
            const int col = n0 + wn + ni * 8 + (lane & 3) * 2;
            const float bx = __ldg(&bias[col]), by = __ldg(&bias[col + 1]);
            float2 r0 = {acc[mi][ni][0] + bx, acc[mi][ni][1] + by};
            float2 r1 = {acc[mi][ni][2] + bx, acc[mi][ni][3] + by};
            *(float2*)&C[(size_t)row * DMODEL + col]       = r0;
            *(float2*)&C[(size_t)(row + 8) * DMODEL + col] = r1;
        }
    }
#undef LOAD_STAGE
}

// ============================================================================
// converters (unchanged)
// ============================================================================
__global__ __launch_bounds__(256)
void split3_rows(const float* __restrict__ X, __nv_bfloat16* __restrict__ O,
                 int kshift)
{
    const int K = 1 << kshift;
    const size_t i4 = ((size_t)blockIdx.x * blockDim.x + threadIdx.x) << 2;
    const size_t row = i4 >> kshift;
    const int col = (int)(i4 & (size_t)(K - 1));
    const float4 v = *(const float4*)&X[i4];
    __nv_bfloat16 h[4], l[4];
    h[0] = __float2bfloat16_rn(v.x); l[0] = __float2bfloat16_rn(v.x - __bfloat162float(h[0]));
    h[1] = __float2bfloat16_rn(v.y); l[1] = __float2bfloat16_rn(v.y - __bfloat162float(h[1]));
    h[2] = __float2bfloat16_rn(v.z); l[2] = __float2bfloat16_rn(v.z - __bfloat162float(h[2]));
    h[3] = __float2bfloat16_rn(v.w); l[3] = __float2bfloat16_rn(v.w - __bfloat162float(h[3]));
    __nv_bfloat16* out = O + row * (size_t)(3 * K);
    *(uint2*)&out[col]         = *(const uint2*)h;
    *(uint2*)&out[K + col]     = *(const uint2*)h;
    *(uint2*)&out[2 * K + col] = *(const uint2*)l;
}

__global__ void splitT3(const float* __restrict__ W, __nv_bfloat16* __restrict__ O,
                        int K, int N)
{
    __shared__ float t[32][33];
    const int n0 = blockIdx.x * 32, k0 = blockIdx.y * 32;
    const int tx = threadIdx.x, ty = threadIdx.y;
#pragma unroll
    for (int r = 0; r < 4; ++r)
        t[ty + 8 * r][tx] = W[(size_t)(k0 + ty + 8 * r) * N + n0 + tx];
    __syncthreads();
#pragma unroll
    for (int r = 0; r < 4; ++r) {
        const int n = n0 + ty + 8 * r, k = k0 + tx;
        const float v = t[tx][ty + 8 * r];
        const __nv_bfloat16 hi = __float2bfloat16_rn(v);
        const __nv_bfloat16 lo = __float2bfloat16_rn(v - __bfloat162float(hi));
        __nv_bfloat16* o = O + (size_t)n * 3 * K;
        o[k]         = hi;
        o[K + k]     = lo;
        o[2 * K + k] = hi;
    }
}

// ============================================================================
// Tensor-core flash attention.
// CTA = 128 q rows x (b, h); 8 warps, 16 q-rows each; kv tiles of 64.
// Split-3 bf16 in registers: S = qh*kh + qh*kl + ql*kh  (and same for PV).
// Smem: Qh/Ql [128][72], Kh/Kl [64][72], Vth/Vtl [64][72] (V transposed).
// Writes sp_a (3-segment) directly.
// ============================================================================
#define LDA 72
#define Q_ELEMS (128 * LDA)
#define K_ELEMS (64 * LDA)
#define ATTN_SMEM_BYTES ((2 * Q_ELEMS + 4 * K_ELEMS) * 2)

__global__ __launch_bounds__(256)
void attn_mma()
{
    extern __shared__ __nv_bfloat16 smb[];
    __nv_bfloat16* Qh  = smb;
    __nv_bfloat16* Ql  = Qh + Q_ELEMS;
    __nv_bfloat16* Kh  = Ql + Q_ELEMS;
    __nv_bfloat16* Kl  = Kh + K_ELEMS;
    __nv_bfloat16* Vth = Kl + K_ELEMS;     // [d][kv] transposed
    __nv_bfloat16* Vtl = Vth + K_ELEMS;

    const int qb   = blockIdx.x;
    const int h    = blockIdx.y;
    const int b    = blockIdx.z;
    const int tid  = threadIdx.x;
    const int wid  = tid >> 5;
    const int lane = tid & 31;
    const int wm   = wid * 16;

    const float* Qg = g_Q + ((size_t)b * SLQ + qb * 128) * DMODEL + h * DHEAD;
    const float* Kg = g_K + (size_t)b * SLKV * DMODEL + h * DHEAD;
    const float* Vg = g_V + (size_t)b * SLKV * DMODEL + h * DHEAD;

    // ---- load Q tile, prescale by 1/8, split to hi/lo ----
#pragma unroll
    for (int i = 0; i < 8; ++i) {
        const int f4  = i * 256 + tid;          // 2048 float4s
        const int row = f4 >> 4;
        const int c4  = (f4 & 15) << 2;
        const float4 v = *(const float4*)&Qg[(size_t)row * DMODEL + c4];
        float val[4] = {v.x * 0.125f, v.y * 0.125f, v.z * 0.125f, v.w * 0.125f};
#pragma unroll
        for (int j = 0; j < 4; ++j) {
            const __nv_bfloat16 hi = __float2bfloat16_rn(val[j]);
            Qh[row * LDA + c4 + j] = hi;
            Ql[row * LDA + c4 + j] = __float2bfloat16_rn(val[j] - __bfloat162float(hi));
        }
    }

    float Sa[8][4], Oa[8][4];
    float mrow[2] = {-3.0e38f, -3.0e38f};
    float lrow[2] = {0.0f, 0.0f};
#pragma unroll
    for (int t = 0; t < 8; ++t)
#pragma unroll
        for (int e = 0; e < 4; ++e) Oa[t][e] = 0.0f;

    for (int kv0 = 0; kv0 < SLKV; kv0 += 64) {
        __syncthreads();   // previous tile's consumers done
        // ---- load K/V tiles, split; V transposed into Vth/Vtl ----
#pragma unroll
        for (int i = 0; i < 4; ++i) {
            const int f4  = i * 256 + tid;      // 1024 float4s
            const int row = f4 >> 4;
            const int c4  = (f4 & 15) << 2;
            const float4 kv4 = *(const float4*)&Kg[(size_t)(kv0 + row) * DMODEL + c4];
            const float4 vv4 = *(const float4*)&Vg[(size_t)(kv0 + row) * DMODEL + c4];
            const float kk[4] = {kv4.x, kv4.y, kv4.z, kv4.w};
            const float vv[4] = {vv4.x, vv4.y, vv4.z, vv4.w};
#pragma unroll
            for (int j = 0; j < 4; ++j) {
                __nv_bfloat16 hi = __float2bfloat16_rn(kk[j]);
                Kh[row * LDA + c4 + j] = hi;
                Kl[row * LDA + c4 + j] = __float2bfloat16_rn(kk[j] - __bfloat162float(hi));
                hi = __float2bfloat16_rn(vv[j]);
                Vth[(c4 + j) * LDA + row] = hi;
                Vtl[(c4 + j) * LDA + row] = __float2bfloat16_rn(vv[j] - __bfloat162float(hi));
            }
        }
        __syncthreads();

        // ---- S = Q3 @ K3^T ----
#pragma unroll
        for (int t = 0; t < 8; ++t)
#pragma unroll
            for (int e = 0; e < 4; ++e) Sa[t][e] = 0.0f;

#pragma unroll
        for (int ks = 0; ks < 4; ++ks) {
            uint32_t aH[4], aL[4];
            const int arow = wm + (lane & 15);
            const int acol = ks * 16 + (lane >> 4) * 8;
            ldmx4(aH, smem_u32(&Qh[arow * LDA + acol]));
            ldmx4(aL, smem_u32(&Ql[arow * LDA + acol]));
#pragma unroll
            for (int np = 0; np < 4; ++np) {
                uint32_t bH[4], bL[4];
                const int brow = np * 16 + ((lane >> 4) & 1) * 8 + (lane & 7);
                const int bcol = ks * 16 + ((lane >> 3) & 1) * 8;
                ldmx4(bH, smem_u32(&Kh[brow * LDA + bcol]));
                ldmx4(bL, smem_u32(&Kl[brow * LDA + bcol]));
#pragma unroll
                for (int hf = 0; hf < 2; ++hf) {
                    float* c = Sa[np * 2 + hf];
                    mma16816(c, aH, &bH[hf * 2]);
                    mma16816(c, aH, &bL[hf * 2]);
                    mma16816(c, aL, &bH[hf * 2]);
                }
            }
        }

        // ---- online softmax (rows r = lane>>2 and r+8) ----
        float mx0 = -3.0e38f, mx1 = -3.0e38f;
#pragma unroll
        for (int t = 0; t < 8; ++t) {
            mx0 = fmaxf(mx0, fmaxf(Sa[t][0], Sa[t][1]));
            mx1 = fmaxf(mx1, fmaxf(Sa[t][2], Sa[t][3]));
        }
        mx0 = fmaxf(mx0, __shfl_xor_sync(0xffffffffu, mx0, 1));
        mx0 = fmaxf(mx0, __shfl_xor_sync(0xffffffffu, mx0, 2));
        mx1 = fmaxf(mx1, __shfl_xor_sync(0xffffffffu, mx1, 1));
        mx1 = fmaxf(mx1, __shfl_xor_sync(0xffffffffu, mx1, 2));

        const float mn0 = fmaxf(mrow[0], mx0);
        const float mn1 = fmaxf(mrow[1], mx1);
        const float al0 = __expf(mrow[0] - mn0);
        const float al1 = __expf(mrow[1] - mn1);
        mrow[0] = mn0; mrow[1] = mn1;

        float sum0 = 0.0f, sum1 = 0.0f;
#pragma unroll
        for (int t = 0; t < 8; ++t) {
            Sa[t][0] = __expf(Sa[t][0] - mn0);
            Sa[t][1] = __expf(Sa[t][1] - mn0);
            Sa[t][2] = __expf(Sa[t][2] - mn1);
            Sa[t][3] = __expf(Sa[t][3] - mn1);
            sum0 += Sa[t][0] + Sa[t][1];
            sum1 += Sa[t][2] + Sa[t][3];
        }
        sum0 += __shfl_xor_sync(0xffffffffu, sum0, 1);
        sum0 += __shfl_xor_sync(0xffffffffu, sum0, 2);
        sum1 += __shfl_xor_sync(0xffffffffu, sum1, 1);
        sum1 += __shfl_xor_sync(0xffffffffu, sum1, 2);
        lrow[0] = lrow[0] * al0 + sum0;
        lrow[1] = lrow[1] * al1 + sum1;

#pragma unroll
        for (int t = 0; t < 8; ++t) {
            Oa[t][0] *= al0; Oa[t][1] *= al0;
            Oa[t][2] *= al1; Oa[t][3] *= al1;
        }

        // ---- O += P3 @ V3 (P fragments from S accumulators) ----
#pragma unroll
        for (int u = 0; u < 4; ++u) {
            uint32_t aH[4], aL[4];
            float lx, ly;
            aH[0] = pack_hi(Sa[2*u][0],   Sa[2*u][1],   lx, ly); aL[0] = pack2(lx, ly);
            aH[1] = pack_hi(Sa[2*u][2],   Sa[2*u][3],   lx, ly); aL[1] = pack2(lx, ly);
            aH[2] = pack_hi(Sa[2*u+1][0], Sa[2*u+1][1], lx, ly); aL[2] = pack2(lx, ly);
            aH[3] = pack_hi(Sa[2*u+1][2], Sa[2*u+1][3], lx, ly); aL[3] = pack2(lx, ly);
#pragma unroll
            for (int np = 0; np < 4; ++np) {
                uint32_t bH[4], bL[4];
                const int brow = np * 16 + ((lane >> 4) & 1) * 8 + (lane & 7);
                const int bcol = u * 16 + ((lane >> 3) & 1) * 8;
                ldmx4(bH, smem_u32(&Vth[brow * LDA + bcol]));
                ldmx4(bL, smem_u32(&Vtl[brow * LDA + bcol]));
#pragma unroll
                for (int hf = 0; hf < 2; ++hf) {
                    float* c = Oa[np * 2 + hf];
                    mma16816(c, aH, &bH[hf * 2]);
                    mma16816(c, aH, &bL[hf * 2]);
                    mma16816(c, aL, &bH[hf * 2]);
                }
            }
        }
    }

    // ---- epilogue: normalize, write 3-segment sp_a directly ----
    const float inv0 = 1.0f / lrow[0];
    const float inv1 = 1.0f / lrow[1];
    const int qrow = qb * 128 + wm + (lane >> 2);
    __nv_bfloat16* out0 = sp_a + ((size_t)b * SLQ + qrow) * (3 * DMODEL) + h * DHEAD;
    __nv_bfloat16* out1 = out0 + (size_t)8 * (3 * DMODEL);
#pragma unroll
    for (int t = 0; t < 8; ++t) {
        const int d = t * 8 + (lane & 3) * 2;
        const float o0 = Oa[t][0] * inv0, o1 = Oa[t][1] * inv0;
        const float o2 = Oa[t][2] * inv1, o3 = Oa[t][3] * inv1;
        float lx, ly;
        uint32_t hi0 = pack_hi(o0, o1, lx, ly);
        uint32_t lo0 = pack2(lx, ly);
        *(uint32_t*)&out0[d]              = hi0;
        *(uint32_t*)&out0[DMODEL + d]     = hi0;
        *(uint32_t*)&out0[2 * DMODEL + d] = lo0;
        uint32_t hi1 = pack_hi(o2, o3, lx, ly);
        uint32_t lo1 = pack2(lx, ly);
        *(uint32_t*)&out1[d]              = hi1;
        *(uint32_t*)&out1[DMODEL + d]     = hi1;
        *(uint32_t*)&out1[2 * DMODEL + d] = lo1;
    }
}

// ============================================================================
// host side
// ============================================================================
extern "C" void kernel_launch(void* const* d_in, const int* in_sizes, int n_in,
                              void* d_out, int out_size)
{
    const float* q  = (const float*)d_in[0];
    const float* k  = (const float*)d_in[1];
    const float* v  = (const float*)d_in[2];
    const float* Wq = (const float*)d_in[3];
    const float* bq = (const float*)d_in[4];
    const float* Wk = (const float*)d_in[5];
    const float* bk = (const float*)d_in[6];
    const float* Wv = (const float*)d_in[7];
    const float* bv = (const float*)d_in[8];
    const float* Wo = (const float*)d_in[9];
    const float* bo = (const float*)d_in[10];
    float* out = (float*)d_out;

    float *gQ, *gK, *gV;
    cudaGetSymbolAddress((void**)&gQ, g_Q);
    cudaGetSymbolAddress((void**)&gK, g_K);
    cudaGetSymbolAddress((void**)&gV, g_V);
    __nv_bfloat16 *pq, *pk, *pv, *pa, *pwq, *pwk, *pwv, *pwo;
    cudaGetSymbolAddress((void**)&pq,  sp_q);
    cudaGetSymbolAddress((void**)&pk,  sp_k);
    cudaGetSymbolAddress((void**)&pv,  sp_v);
    cudaGetSymbolAddress((void**)&pa,  sp_a);
    cudaGetSymbolAddress((void**)&pwq, tw_q);
    cudaGetSymbolAddress((void**)&pwk, tw_k);
    cudaGetSymbolAddress((void**)&pwv, tw_v);
    cudaGetSymbolAddress((void**)&pwo, tw_o);

    cudaFuncSetAttribute(attn_mma, cudaFuncAttributeMaxDynamicSharedMemorySize,
                         ATTN_SMEM_BYTES);

    // 1) split inputs + weights into 3-segment bf16
    split3_rows<<<(NB * SLQ * DMODEL) / 1024, 256>>>(q, pq, 10);
    split3_rows<<<(NB * SLKV * DIMG) / 1024, 256>>>(k, pk, 9);
    split3_rows<<<(NB * SLKV * DIMG) / 1024, 256>>>(v, pv, 9);
    splitT3<<<dim3(DMODEL / 32, DMODEL / 32), dim3(32, 8)>>>(Wq, pwq, DMODEL, DMODEL);
    splitT3<<<dim3(DMODEL / 32, DIMG / 32),   dim3(32, 8)>>>(Wk, pwk, DIMG, DMODEL);
    splitT3<<<dim3(DMODEL / 32, DIMG / 32),   dim3(32, 8)>>>(Wv, pwv, DIMG, DMODEL);
    splitT3<<<dim3(DMODEL / 32, DMODEL / 32), dim3(32, 8)>>>(Wo, pwo, DMODEL, DMODEL);

    // 2) projections on HMMA tensor cores (K' = 3K)
    gemm_mma<<<dim3(DMODEL / 128, NB * SLQ / 128), 256>>>(pq, pwq, bq, gQ, 3 * DMODEL);
    gemm_mma<<<dim3(DMODEL / 128, NB * SLKV / 128), 256>>>(pk, pwk, bk, gK, 3 * DIMG);
    gemm_mma<<<dim3(DMODEL / 128, NB * SLKV / 128), 256>>>(pv, pwv, bv, gV, 3 * DIMG);

    // 3) tensor-core attention -> sp_a (3-segment, GEMM-ready)
    attn_mma<<<dim3(SLQ / 128, NH, NB), 256, ATTN_SMEM_BYTES>>>();

    // 4) output projection
    gemm_mma<<<dim3(DMODEL / 128, NB * SLQ / 128), 256>>>(pa, pwo, bo, out, 3 * DMODEL);
}

// round 10
// speedup vs baseline: 2.0114x; 1.0564x over previous
#include <cuda_runtime.h>
#include <cuda_bf16.h>
#include <cstdint>
#include <cstddef>

#define NB     8
#define NH     16
#define SLQ    2048
#define SLKV   1024
#define DMODEL 1024
#define DIMG   512
#define DHEAD  64

// ---------------- scratch (allocation-free rule: __device__ globals) ----------
__device__ float g_Q[(size_t)NB * SLQ * DMODEL];
__device__ float g_K[(size_t)NB * SLKV * DMODEL];
__device__ float g_V[(size_t)NB * SLKV * DMODEL];

// 3-segment split operands: A3 = [hi | hi | lo], W3t = [hi | lo | hi]
__device__ __align__(128) __nv_bfloat16 sp_q[(size_t)NB * SLQ  * 3 * DMODEL];
__device__ __align__(128) __nv_bfloat16 sp_k[(size_t)NB * SLKV * 3 * DIMG];
__device__ __align__(128) __nv_bfloat16 sp_v[(size_t)NB * SLKV * 3 * DIMG];
__device__ __align__(128) __nv_bfloat16 sp_a[(size_t)NB * SLQ  * 3 * DMODEL];
__device__ __align__(128) __nv_bfloat16 tw_q[(size_t)DMODEL * 3 * DMODEL];
__device__ __align__(128) __nv_bfloat16 tw_k[(size_t)DMODEL * 3 * DIMG];
__device__ __align__(128) __nv_bfloat16 tw_v[(size_t)DMODEL * 3 * DIMG];
__device__ __align__(128) __nv_bfloat16 tw_o[(size_t)DMODEL * 3 * DMODEL];

// ============================================================================
// low-level helpers (compute_103-safe)
// ============================================================================
__device__ __forceinline__ uint32_t smem_u32(const void* p) {
    return (uint32_t)__cvta_generic_to_shared(p);
}
__device__ __forceinline__ void cpa16(uint32_t s, const void* g) {
    asm volatile("cp.async.cg.shared.global [%0], [%1], 16;" :: "r"(s), "l"(g));
}
__device__ __forceinline__ void cpa_commit() {
    asm volatile("cp.async.commit_group;" ::: "memory");
}
__device__ __forceinline__ void cpa_wait2() {
    asm volatile("cp.async.wait_group 2;" ::: "memory");
}
__device__ __forceinline__ void cpa_wait1() {
    asm volatile("cp.async.wait_group 1;" ::: "memory");
}
__device__ __forceinline__ void ldmx4(uint32_t* r, uint32_t addr) {
    asm volatile("ldmatrix.sync.aligned.m8n8.x4.shared.b16 {%0,%1,%2,%3}, [%4];"
                 : "=r"(r[0]), "=r"(r[1]), "=r"(r[2]), "=r"(r[3]) : "r"(addr));
}
__device__ __forceinline__ void mma16816(float* c, const uint32_t* a, const uint32_t* b) {
    asm volatile("mma.sync.aligned.m16n8k16.row.col.f32.bf16.bf16.f32 "
                 "{%0,%1,%2,%3}, {%4,%5,%6,%7}, {%8,%9}, {%0,%1,%2,%3};"
                 : "+f"(c[0]), "+f"(c[1]), "+f"(c[2]), "+f"(c[3])
                 : "r"(a[0]), "r"(a[1]), "r"(a[2]), "r"(a[3]),
                   "r"(b[0]), "r"(b[1]));
}
__device__ __forceinline__ uint32_t pack_hi(float x, float y, float& lx, float& ly) {
    __nv_bfloat162 h;
    h.x = __float2bfloat16_rn(x);
    h.y = __float2bfloat16_rn(y);
    lx = x - __bfloat162float(h.x);
    ly = y - __bfloat162float(h.y);
    return *(uint32_t*)&h;
}
__device__ __forceinline__ uint32_t pack2(float x, float y) {
    __nv_bfloat162 h;
    h.x = __float2bfloat16_rn(x);
    h.y = __float2bfloat16_rn(y);
    return *(uint32_t*)&h;
}

// ============================================================================
// bf16 mma.sync GEMM v2: C[M,1024] = A3[M,K3] @ B3t[1024,K3]^T + bias
// CTA tile 128(M) x 256(N), BK=32, 8 warps (2x4) each 64x64,
// 4-stage cp.async pipeline, single __syncthreads per K-iter.
// ============================================================================
#define BK      32
#define LDT     40                       // 32 + 8 pad -> conflict-free ldmatrix
#define GTN     256
#define STAGE_E ((128 + GTN) * LDT)      // bf16 elems per stage
#define GEMM_SMEM_BYTES (4 * STAGE_E * 2)

__global__ __launch_bounds__(256, 1)
void gemm_mma(const __nv_bfloat16* __restrict__ A,
              const __nv_bfloat16* __restrict__ B,
              const float* __restrict__ bias,
              float* __restrict__ C, int K2)
{
    extern __shared__ __nv_bfloat16 sg[];

    const int tid  = threadIdx.x;
    const int wid  = tid >> 5;
    const int lane = tid & 31;
    const int wm   = (wid >> 2) * 64;      // 0, 64
    const int wn   = (wid & 3) * 64;       // 0..192
    const int m0   = blockIdx.y * 128;
    const int n0   = blockIdx.x * GTN;
    const int nIter = K2 / BK;

    const int lr = tid >> 2;               // 0..63
    const int kc = (tid & 3) << 3;         // 0,8,16,24

    float acc[4][8][4];
#pragma unroll
    for (int mi = 0; mi < 4; ++mi)
#pragma unroll
        for (int ni = 0; ni < 8; ++ni)
#pragma unroll
            for (int e = 0; e < 4; ++e) acc[mi][ni][e] = 0.0f;

#define LOAD_STAGE(s, kk)                                                      \
    {                                                                          \
        __nv_bfloat16* As_ = sg + (s) * STAGE_E;                               \
        __nv_bfloat16* Bs_ = As_ + 128 * LDT;                                  \
        _Pragma("unroll")                                                      \
        for (int i = 0; i < 2; ++i)                                            \
            cpa16(smem_u32(&As_[(lr + i * 64) * LDT + kc]),                    \
                  &A[(size_t)(m0 + lr + i * 64) * K2 + (kk) + kc]);            \
        _Pragma("unroll")                                                      \
        for (int i = 0; i < 4; ++i)                                            \
            cpa16(smem_u32(&Bs_[(lr + i * 64) * LDT + kc]),                    \
                  &B[(size_t)(n0 + lr + i * 64) * K2 + (kk) + kc]);            \
    }

    // prologue: stages 0..2 (one commit group per stage)
    LOAD_STAGE(0, 0);        cpa_commit();
    LOAD_STAGE(1, BK);       cpa_commit();
    LOAD_STAGE(2, 2 * BK);   cpa_commit();

    for (int it = 0; it < nIter; ++it) {
        cpa_wait2();          // stage `it` complete (empty-commit keeps count)
        __syncthreads();      // all warps done with stage (it-1) -> safe reload
        if (it + 3 < nIter) LOAD_STAGE((it + 3) & 3, (it + 3) * BK);
        cpa_commit();         // committed every iter (possibly empty group)

        const __nv_bfloat16* As = sg + (it & 3) * STAGE_E;
        const __nv_bfloat16* Bs = As + 128 * LDT;
#pragma unroll
        for (int ks = 0; ks < 2; ++ks) {
            uint32_t af[4][4], bf[4][4];
#pragma unroll
            for (int mi = 0; mi < 4; ++mi)
                ldmx4(af[mi], smem_u32(&As[(wm + mi * 16 + (lane & 15)) * LDT +
                                           ks * 16 + (lane >> 4) * 8]));
#pragma unroll
            for (int np = 0; np < 4; ++np)
                ldmx4(bf[np], smem_u32(&Bs[(wn + np * 16 + ((lane >> 4) & 1) * 8 +
                                            (lane & 7)) * LDT +
                                           ks * 16 + ((lane >> 3) & 1) * 8]));
#pragma unroll
            for (int mi = 0; mi < 4; ++mi)
#pragma unroll
                for (int ni = 0; ni < 8; ++ni)
                    mma16816(acc[mi][ni], af[mi], &bf[ni >> 1][(ni & 1) * 2]);
        }
    }

    // epilogue
#pragma unroll
    for (int mi = 0; mi < 4; ++mi) {
        const int row = m0 + wm + mi * 16 + (lane >> 2);
#pragma unroll
        for (int ni = 0; ni < 8; ++ni) {
            const int col = n0 + wn + ni * 8 + (lane & 3) * 2;
            const float bx = __ldg(&bias[col]), by = __ldg(&bias[col + 1]);
            float2 r0 = {acc[mi][ni][0] + bx, acc[mi][ni][1] + by};
            float2 r1 = {acc[mi][ni][2] + bx, acc[mi][ni][3] + by};
            *(float2*)&C[(size_t)row * DMODEL + col]       = r0;
            *(float2*)&C[(size_t)(row + 8) * DMODEL + col] = r1;
        }
    }
#undef LOAD_STAGE
}

// ============================================================================
// converters (unchanged)
// ============================================================================
__global__ __launch_bounds__(256)
void split3_rows(const float* __restrict__ X, __nv_bfloat16* __restrict__ O,
                 int kshift)
{
    const int K = 1 << kshift;
    const size_t i4 = ((size_t)blockIdx.x * blockDim.x + threadIdx.x) << 2;
    const size_t row = i4 >> kshift;
    const int col = (int)(i4 & (size_t)(K - 1));
    const float4 v = *(const float4*)&X[i4];
    __nv_bfloat16 h[4], l[4];
    h[0] = __float2bfloat16_rn(v.x); l[0] = __float2bfloat16_rn(v.x - __bfloat162float(h[0]));
    h[1] = __float2bfloat16_rn(v.y); l[1] = __float2bfloat16_rn(v.y - __bfloat162float(h[1]));
    h[2] = __float2bfloat16_rn(v.z); l[2] = __float2bfloat16_rn(v.z - __bfloat162float(h[2]));
    h[3] = __float2bfloat16_rn(v.w); l[3] = __float2bfloat16_rn(v.w - __bfloat162float(h[3]));
    __nv_bfloat16* out = O + row * (size_t)(3 * K);
    *(uint2*)&out[col]         = *(const uint2*)h;
    *(uint2*)&out[K + col]     = *(const uint2*)h;
    *(uint2*)&out[2 * K + col] = *(const uint2*)l;
}

__global__ void splitT3(const float* __restrict__ W, __nv_bfloat16* __restrict__ O,
                        int K, int N)
{
    __shared__ float t[32][33];
    const int n0 = blockIdx.x * 32, k0 = blockIdx.y * 32;
    const int tx = threadIdx.x, ty = threadIdx.y;
#pragma unroll
    for (int r = 0; r < 4; ++r)
        t[ty + 8 * r][tx] = W[(size_t)(k0 + ty + 8 * r) * N + n0 + tx];
    __syncthreads();
#pragma unroll
    for (int r = 0; r < 4; ++r) {
        const int n = n0 + ty + 8 * r, k = k0 + tx;
        const float v = t[tx][ty + 8 * r];
        const __nv_bfloat16 hi = __float2bfloat16_rn(v);
        const __nv_bfloat16 lo = __float2bfloat16_rn(v - __bfloat162float(hi));
        __nv_bfloat16* o = O + (size_t)n * 3 * K;
        o[k]         = hi;
        o[K + k]     = lo;
        o[2 * K + k] = hi;
    }
}

// ============================================================================
// Tensor-core flash attention (unchanged from round 7 — verified)
// ============================================================================
#define LDA 72
#define Q_ELEMS (128 * LDA)
#define K_ELEMS (64 * LDA)
#define ATTN_SMEM_BYTES ((2 * Q_ELEMS + 4 * K_ELEMS) * 2)

__global__ __launch_bounds__(256)
void attn_mma()
{
    extern __shared__ __nv_bfloat16 smb[];
    __nv_bfloat16* Qh  = smb;
    __nv_bfloat16* Ql  = Qh + Q_ELEMS;
    __nv_bfloat16* Kh  = Ql + Q_ELEMS;
    __nv_bfloat16* Kl  = Kh + K_ELEMS;
    __nv_bfloat16* Vth = Kl + K_ELEMS;
    __nv_bfloat16* Vtl = Vth + K_ELEMS;

    const int qb   = blockIdx.x;
    const int h    = blockIdx.y;
    const int b    = blockIdx.z;
    const int tid  = threadIdx.x;
    const int wid  = tid >> 5;
    const int lane = tid & 31;
    const int wm   = wid * 16;

    const float* Qg = g_Q + ((size_t)b * SLQ + qb * 128) * DMODEL + h * DHEAD;
    const float* Kg = g_K + (size_t)b * SLKV * DMODEL + h * DHEAD;
    const float* Vg = g_V + (size_t)b * SLKV * DMODEL + h * DHEAD;

#pragma unroll
    for (int i = 0; i < 8; ++i) {
        const int f4  = i * 256 + tid;
        const int row = f4 >> 4;
        const int c4  = (f4 & 15) << 2;
        const float4 v = *(const float4*)&Qg[(size_t)row * DMODEL + c4];
        float val[4] = {v.x * 0.125f, v.y * 0.125f, v.z * 0.125f, v.w * 0.125f};
#pragma unroll
        for (int j = 0; j < 4; ++j) {
            const __nv_bfloat16 hi = __float2bfloat16_rn(val[j]);
            Qh[row * LDA + c4 + j] = hi;
            Ql[row * LDA + c4 + j] = __float2bfloat16_rn(val[j] - __bfloat162float(hi));
        }
    }

    float Sa[8][4], Oa[8][4];
    float mrow[2] = {-3.0e38f, -3.0e38f};
    float lrow[2] = {0.0f, 0.0f};
#pragma unroll
    for (int t = 0; t < 8; ++t)
#pragma unroll
        for (int e = 0; e < 4; ++e) Oa[t][e] = 0.0f;

    for (int kv0 = 0; kv0 < SLKV; kv0 += 64) {
        __syncthreads();
#pragma unroll
        for (int i = 0; i < 4; ++i) {
            const int f4  = i * 256 + tid;
            const int row = f4 >> 4;
            const int c4  = (f4 & 15) << 2;
            const float4 kv4 = *(const float4*)&Kg[(size_t)(kv0 + row) * DMODEL + c4];
            const float4 vv4 = *(const float4*)&Vg[(size_t)(kv0 + row) * DMODEL + c4];
            const float kk[4] = {kv4.x, kv4.y, kv4.z, kv4.w};
            const float vv[4] = {vv4.x, vv4.y, vv4.z, vv4.w};
#pragma unroll
            for (int j = 0; j < 4; ++j) {
                __nv_bfloat16 hi = __float2bfloat16_rn(kk[j]);
                Kh[row * LDA + c4 + j] = hi;
                Kl[row * LDA + c4 + j] = __float2bfloat16_rn(kk[j] - __bfloat162float(hi));
                hi = __float2bfloat16_rn(vv[j]);
                Vth[(c4 + j) * LDA + row] = hi;
                Vtl[(c4 + j) * LDA + row] = __float2bfloat16_rn(vv[j] - __bfloat162float(hi));
            }
        }
        __syncthreads();

#pragma unroll
        for (int t = 0; t < 8; ++t)
#pragma unroll
            for (int e = 0; e < 4; ++e) Sa[t][e] = 0.0f;

#pragma unroll
        for (int ks = 0; ks < 4; ++ks) {
            uint32_t aH[4], aL[4];
            const int arow = wm + (lane & 15);
            const int acol = ks * 16 + (lane >> 4) * 8;
            ldmx4(aH, smem_u32(&Qh[arow * LDA + acol]));
            ldmx4(aL, smem_u32(&Ql[arow * LDA + acol]));
#pragma unroll
            for (int np = 0; np < 4; ++np) {
                uint32_t bH[4], bL[4];
                const int brow = np * 16 + ((lane >> 4) & 1) * 8 + (lane & 7);
                const int bcol = ks * 16 + ((lane >> 3) & 1) * 8;
                ldmx4(bH, smem_u32(&Kh[brow * LDA + bcol]));
                ldmx4(bL, smem_u32(&Kl[brow * LDA + bcol]));
#pragma unroll
                for (int hf = 0; hf < 2; ++hf) {
                    float* c = Sa[np * 2 + hf];
                    mma16816(c, aH, &bH[hf * 2]);
                    mma16816(c, aH, &bL[hf * 2]);
                    mma16816(c, aL, &bH[hf * 2]);
                }
            }
        }

        float mx0 = -3.0e38f, mx1 = -3.0e38f;
#pragma unroll
        for (int t = 0; t < 8; ++t) {
            mx0 = fmaxf(mx0, fmaxf(Sa[t][0], Sa[t][1]));
            mx1 = fmaxf(mx1, fmaxf(Sa[t][2], Sa[t][3]));
        }
        mx0 = fmaxf(mx0, __shfl_xor_sync(0xffffffffu, mx0, 1));
        mx0 = fmaxf(mx0, __shfl_xor_sync(0xffffffffu, mx0, 2));
        mx1 = fmaxf(mx1, __shfl_xor_sync(0xffffffffu, mx1, 1));
        mx1 = fmaxf(mx1, __shfl_xor_sync(0xffffffffu, mx1, 2));

        const float mn0 = fmaxf(mrow[0], mx0);
        const float mn1 = fmaxf(mrow[1], mx1);
        const float al0 = __expf(mrow[0] - mn0);
        const float al1 = __expf(mrow[1] - mn1);
        mrow[0] = mn0; mrow[1] = mn1;

        float sum0 = 0.0f, sum1 = 0.0f;
#pragma unroll
        for (int t = 0; t < 8; ++t) {
            Sa[t][0] = __expf(Sa[t][0] - mn0);
            Sa[t][1] = __expf(Sa[t][1] - mn0);
            Sa[t][2] = __expf(Sa[t][2] - mn1);
            Sa[t][3] = __expf(Sa[t][3] - mn1);
            sum0 += Sa[t][0] + Sa[t][1];
            sum1 += Sa[t][2] + Sa[t][3];
        }
        sum0 += __shfl_xor_sync(0xffffffffu, sum0, 1);
        sum0 += __shfl_xor_sync(0xffffffffu, sum0, 2);
        sum1 += __shfl_xor_sync(0xffffffffu, sum1, 1);
        sum1 += __shfl_xor_sync(0xffffffffu, sum1, 2);
        lrow[0] = lrow[0] * al0 + sum0;
        lrow[1] = lrow[1] * al1 + sum1;

#pragma unroll
        for (int t = 0; t < 8; ++t) {
            Oa[t][0] *= al0; Oa[t][1] *= al0;
            Oa[t][2] *= al1; Oa[t][3] *= al1;
        }

#pragma unroll
        for (int u = 0; u < 4; ++u) {
            uint32_t aH[4], aL[4];
            float lx, ly;
            aH[0] = pack_hi(Sa[2*u][0],   Sa[2*u][1],   lx, ly); aL[0] = pack2(lx, ly);
            aH[1] = pack_hi(Sa[2*u][2],   Sa[2*u][3],   lx, ly); aL[1] = pack2(lx, ly);
            aH[2] = pack_hi(Sa[2*u+1][0], Sa[2*u+1][1], lx, ly); aL[2] = pack2(lx, ly);
            aH[3] = pack_hi(Sa[2*u+1][2], Sa[2*u+1][3], lx, ly); aL[3] = pack2(lx, ly);
#pragma unroll
            for (int np = 0; np < 4; ++np) {
                uint32_t bH[4], bL[4];
                const int brow = np * 16 + ((lane >> 4) & 1) * 8 + (lane & 7);
                const int bcol = u * 16 + ((lane >> 3) & 1) * 8;
                ldmx4(bH, smem_u32(&Vth[brow * LDA + bcol]));
                ldmx4(bL, smem_u32(&Vtl[brow * LDA + bcol]));
#pragma unroll
                for (int hf = 0; hf < 2; ++hf) {
                    float* c = Oa[np * 2 + hf];
                    mma16816(c, aH, &bH[hf * 2]);
                    mma16816(c, aH, &bL[hf * 2]);
                    mma16816(c, aL, &bH[hf * 2]);
                }
            }
        }
    }

    const float inv0 = 1.0f / lrow[0];
    const float inv1 = 1.0f / lrow[1];
    const int qrow = qb * 128 + wm + (lane >> 2);
    __nv_bfloat16* out0 = sp_a + ((size_t)b * SLQ + qrow) * (3 * DMODEL) + h * DHEAD;
    __nv_bfloat16* out1 = out0 + (size_t)8 * (3 * DMODEL);
#pragma unroll
    for (int t = 0; t < 8; ++t) {
        const int d = t * 8 + (lane & 3) * 2;
        const float o0 = Oa[t][0] * inv0, o1 = Oa[t][1] * inv0;
        const float o2 = Oa[t][2] * inv1, o3 = Oa[t][3] * inv1;
        float lx, ly;
        uint32_t hi0 = pack_hi(o0, o1, lx, ly);
        uint32_t lo0 = pack2(lx, ly);
        *(uint32_t*)&out0[d]              = hi0;
        *(uint32_t*)&out0[DMODEL + d]     = hi0;
        *(uint32_t*)&out0[2 * DMODEL + d] = lo0;
        uint32_t hi1 = pack_hi(o2, o3, lx, ly);
        uint32_t lo1 = pack2(lx, ly);
        *(uint32_t*)&out1[d]              = hi1;
        *(uint32_t*)&out1[DMODEL + d]     = hi1;
        *(uint32_t*)&out1[2 * DMODEL + d] = lo1;
    }
}

// ============================================================================
// host side
// ============================================================================
extern "C" void kernel_launch(void* const* d_in, const int* in_sizes, int n_in,
                              void* d_out, int out_size)
{
    const float* q  = (const float*)d_in[0];
    const float* k  = (const float*)d_in[1];
    const float* v  = (const float*)d_in[2];
    const float* Wq = (const float*)d_in[3];
    const float* bq = (const float*)d_in[4];
    const float* Wk = (const float*)d_in[5];
    const float* bk = (const float*)d_in[6];
    const float* Wv = (const float*)d_in[7];
    const float* bv = (const float*)d_in[8];
    const float* Wo = (const float*)d_in[9];
    const float* bo = (const float*)d_in[10];
    float* out = (float*)d_out;

    float *gQ, *gK, *gV;
    cudaGetSymbolAddress((void**)&gQ, g_Q);
    cudaGetSymbolAddress((void**)&gK, g_K);
    cudaGetSymbolAddress((void**)&gV, g_V);
    __nv_bfloat16 *pq, *pk, *pv, *pa, *pwq, *pwk, *pwv, *pwo;
    cudaGetSymbolAddress((void**)&pq,  sp_q);
    cudaGetSymbolAddress((void**)&pk,  sp_k);
    cudaGetSymbolAddress((void**)&pv,  sp_v);
    cudaGetSymbolAddress((void**)&pa,  sp_a);
    cudaGetSymbolAddress((void**)&pwq, tw_q);
    cudaGetSymbolAddress((void**)&pwk, tw_k);
    cudaGetSymbolAddress((void**)&pwv, tw_v);
    cudaGetSymbolAddress((void**)&pwo, tw_o);

    cudaFuncSetAttribute(gemm_mma, cudaFuncAttributeMaxDynamicSharedMemorySize,
                         GEMM_SMEM_BYTES);
    cudaFuncSetAttribute(attn_mma, cudaFuncAttributeMaxDynamicSharedMemorySize,
                         ATTN_SMEM_BYTES);

    // launch order arranged so launch #6 (ncu -s 5 -c 1) is the Q-proj GEMM
    split3_rows<<<(NB * SLQ * DMODEL) / 1024, 256>>>(q, pq, 10);                      // 1
    splitT3<<<dim3(DMODEL / 32, DMODEL / 32), dim3(32, 8)>>>(Wq, pwq, DMODEL, DMODEL);// 2
    split3_rows<<<(NB * SLKV * DIMG) / 1024, 256>>>(k, pk, 9);                        // 3
    splitT3<<<dim3(DMODEL / 32, DIMG / 32),   dim3(32, 8)>>>(Wk, pwk, DIMG, DMODEL);  // 4
    split3_rows<<<(NB * SLKV * DIMG) / 1024, 256>>>(v, pv, 9);                        // 5

    gemm_mma<<<dim3(DMODEL / GTN, NB * SLQ / 128), 256, GEMM_SMEM_BYTES>>>(           // 6 <- profiled
        pq, pwq, bq, gQ, 3 * DMODEL);

    splitT3<<<dim3(DMODEL / 32, DIMG / 32),   dim3(32, 8)>>>(Wv, pwv, DIMG, DMODEL);  // 7
    splitT3<<<dim3(DMODEL / 32, DMODEL / 32), dim3(32, 8)>>>(Wo, pwo, DMODEL, DMODEL);// 8

    gemm_mma<<<dim3(DMODEL / GTN, NB * SLKV / 128), 256, GEMM_SMEM_BYTES>>>(          // 9
        pk, pwk, bk, gK, 3 * DIMG);
    gemm_mma<<<dim3(DMODEL / GTN, NB * SLKV / 128), 256, GEMM_SMEM_BYTES>>>(          // 10
        pv, pwv, bv, gV, 3 * DIMG);

    attn_mma<<<dim3(SLQ / 128, NH, NB), 256, ATTN_SMEM_BYTES>>>();                    // 11

    gemm_mma<<<dim3(DMODEL / GTN, NB * SLQ / 128), 256, GEMM_SMEM_BYTES>>>(           // 12
        pa, pwo, bo, out, 3 * DMODEL);
}

// round 16
// speedup vs baseline: 2.1311x; 1.0595x over previous
#include <cuda_runtime.h>
#include <cuda_bf16.h>
#include <cstdint>
#include <cstddef>

#define NB     8
#define NH     16
#define SLQ    2048
#define SLKV   1024
#define DMODEL 1024
#define DIMG   512
#define DHEAD  64

// ---------------- scratch (allocation-free rule: __device__ globals) ----------
__device__ float g_Q[(size_t)NB * SLQ * DMODEL];
__device__ float g_K[(size_t)NB * SLKV * DMODEL];
__device__ float g_V[(size_t)NB * SLKV * DMODEL];

// 3-segment split operands for GEMMs
__device__ __align__(128) __nv_bfloat16 sp_q[(size_t)NB * SLQ  * 3 * DMODEL];
__device__ __align__(128) __nv_bfloat16 sp_k[(size_t)NB * SLKV * 3 * DIMG];
__device__ __align__(128) __nv_bfloat16 sp_v[(size_t)NB * SLKV * 3 * DIMG];
__device__ __align__(128) __nv_bfloat16 sp_a[(size_t)NB * SLQ  * 3 * DMODEL];
__device__ __align__(128) __nv_bfloat16 tw_q[(size_t)DMODEL * 3 * DMODEL];
__device__ __align__(128) __nv_bfloat16 tw_k[(size_t)DMODEL * 3 * DIMG];
__device__ __align__(128) __nv_bfloat16 tw_v[(size_t)DMODEL * 3 * DIMG];
__device__ __align__(128) __nv_bfloat16 tw_o[(size_t)DMODEL * 3 * DMODEL];

// pre-split attention operands (conversion done ONCE, not per q-block)
__device__ __align__(128) __nv_bfloat16 qs_h[(size_t)NB * SLQ * DMODEL];   // prescaled by 1/8
__device__ __align__(128) __nv_bfloat16 qs_l[(size_t)NB * SLQ * DMODEL];
__device__ __align__(128) __nv_bfloat16 ks_h[(size_t)NB * SLKV * DMODEL];
__device__ __align__(128) __nv_bfloat16 ks_l[(size_t)NB * SLKV * DMODEL];
__device__ __align__(128) __nv_bfloat16 vt_h[(size_t)NB * NH * DHEAD * SLKV]; // [b,h][d][kv]
__device__ __align__(128) __nv_bfloat16 vt_l[(size_t)NB * NH * DHEAD * SLKV];

// ============================================================================
// low-level helpers (compute_103-safe)
// ============================================================================
__device__ __forceinline__ uint32_t smem_u32(const void* p) {
    return (uint32_t)__cvta_generic_to_shared(p);
}
__device__ __forceinline__ void cpa16(uint32_t s, const void* g) {
    asm volatile("cp.async.cg.shared.global [%0], [%1], 16;" :: "r"(s), "l"(g));
}
__device__ __forceinline__ void cpa_commit() {
    asm volatile("cp.async.commit_group;" ::: "memory");
}
__device__ __forceinline__ void cpa_wait2() {
    asm volatile("cp.async.wait_group 2;" ::: "memory");
}
__device__ __forceinline__ void cpa_wait1() {
    asm volatile("cp.async.wait_group 1;" ::: "memory");
}
__device__ __forceinline__ void ldmx4(uint32_t* r, uint32_t addr) {
    asm volatile("ldmatrix.sync.aligned.m8n8.x4.shared.b16 {%0,%1,%2,%3}, [%4];"
                 : "=r"(r[0]), "=r"(r[1]), "=r"(r[2]), "=r"(r[3]) : "r"(addr));
}
__device__ __forceinline__ void mma16816(float* c, const uint32_t* a, const uint32_t* b) {
    asm volatile("mma.sync.aligned.m16n8k16.row.col.f32.bf16.bf16.f32 "
                 "{%0,%1,%2,%3}, {%4,%5,%6,%7}, {%8,%9}, {%0,%1,%2,%3};"
                 : "+f"(c[0]), "+f"(c[1]), "+f"(c[2]), "+f"(c[3])
                 : "r"(a[0]), "r"(a[1]), "r"(a[2]), "r"(a[3]),
                   "r"(b[0]), "r"(b[1]));
}
__device__ __forceinline__ uint32_t pack_hi(float x, float y, float& lx, float& ly) {
    __nv_bfloat162 h;
    h.x = __float2bfloat16_rn(x);
    h.y = __float2bfloat16_rn(y);
    lx = x - __bfloat162float(h.x);
    ly = y - __bfloat162float(h.y);
    return *(uint32_t*)&h;
}
__device__ __forceinline__ uint32_t pack2(float x, float y) {
    __nv_bfloat162 h;
    h.x = __float2bfloat16_rn(x);
    h.y = __float2bfloat16_rn(y);
    return *(uint32_t*)&h;
}

// ============================================================================
// bf16 mma.sync GEMM (unchanged — verified at 1830us baseline)
// ============================================================================
#define BK      32
#define LDT     40
#define GTN     256
#define STAGE_E ((128 + GTN) * LDT)
#define GEMM_SMEM_BYTES (4 * STAGE_E * 2)

__global__ __launch_bounds__(256, 1)
void gemm_mma(const __nv_bfloat16* __restrict__ A,
              const __nv_bfloat16* __restrict__ B,
              const float* __restrict__ bias,
              float* __restrict__ C, int K2)
{
    extern __shared__ __nv_bfloat16 sg[];

    const int tid  = threadIdx.x;
    const int wid  = tid >> 5;
    const int lane = tid & 31;
    const int wm   = (wid >> 2) * 64;
    const int wn   = (wid & 3) * 64;
    const int m0   = blockIdx.y * 128;
    const int n0   = blockIdx.x * GTN;
    const int nIter = K2 / BK;

    const int lr = tid >> 2;
    const int kc = (tid & 3) << 3;

    float acc[4][8][4];
#pragma unroll
    for (int mi = 0; mi < 4; ++mi)
#pragma unroll
        for (int ni = 0; ni < 8; ++ni)
#pragma unroll
            for (int e = 0; e < 4; ++e) acc[mi][ni][e] = 0.0f;

#define LOAD_STAGE(s, kk)                                                      \
    {                                                                          \
        __nv_bfloat16* As_ = sg + (s) * STAGE_E;                               \
        __nv_bfloat16* Bs_ = As_ + 128 * LDT;                                  \
        _Pragma("unroll")                                                      \
        for (int i = 0; i < 2; ++i)                                            \
            cpa16(smem_u32(&As_[(lr + i * 64) * LDT + kc]),                    \
                  &A[(size_t)(m0 + lr + i * 64) * K2 + (kk) + kc]);            \
        _Pragma("unroll")                                                      \
        for (int i = 0; i < 4; ++i)                                            \
            cpa16(smem_u32(&Bs_[(lr + i * 64) * LDT + kc]),                    \
                  &B[(size_t)(n0 + lr + i * 64) * K2 + (kk) + kc]);            \
    }

    LOAD_STAGE(0, 0);        cpa_commit();
    LOAD_STAGE(1, BK);       cpa_commit();
    LOAD_STAGE(2, 2 * BK);   cpa_commit();

    for (int it = 0; it < nIter; ++it) {
        cpa_wait2();
        __syncthreads();
        if (it + 3 < nIter) LOAD_STAGE((it + 3) & 3, (it + 3) * BK);
        cpa_commit();

        const __nv_bfloat16* As = sg + (it & 3) * STAGE_E;
        const __nv_bfloat16* Bs = As + 128 * LDT;
#pragma unroll
        for (int ks = 0; ks < 2; ++ks) {
            uint32_t af[4][4], bf[4][4];
#pragma unroll
            for (int mi = 0; mi < 4; ++mi)
                ldmx4(af[mi], smem_u32(&As[(wm + mi * 16 + (lane & 15)) * LDT +
                                           ks * 16 + (lane >> 4) * 8]));
#pragma unroll
            for (int np = 0; np < 4; ++np)
                ldmx4(bf[np], smem_u32(&Bs[(wn + np * 16 + ((lane >> 4) & 1) * 8 +
                                            (lane & 7)) * LDT +
                                           ks * 16 + ((lane >> 3) & 1) * 8]));
#pragma unroll
            for (int mi = 0; mi < 4; ++mi)
#pragma unroll
                for (int ni = 0; ni < 8; ++ni)
                    mma16816(acc[mi][ni], af[mi], &bf[ni >> 1][(ni & 1) * 2]);
        }
    }

#pragma unroll
    for (int mi = 0; mi < 4; ++mi) {
        const int row = m0 + wm + mi * 16 + (lane >> 2);
#pragma unroll
        for (int ni = 0; ni < 8; ++ni) {
            const int col = n0 + wn + ni * 8 + (lane & 3) * 2;
            const float bx = __ldg(&bias[col]), by = __ldg(&bias[col + 1]);
            float2 r0 = {acc[mi][ni][0] + bx, acc[mi][ni][1] + by};
            float2 r1 = {acc[mi][ni][2] + bx, acc[mi][ni][3] + by};
            *(float2*)&C[(size_t)row * DMODEL + col]       = r0;
            *(float2*)&C[(size_t)(row + 8) * DMODEL + col] = r1;
        }
    }
#undef LOAD_STAGE
}

// ============================================================================
// converters
// ============================================================================
__global__ __launch_bounds__(256)
void split3_rows(const float* __restrict__ X, __nv_bfloat16* __restrict__ O,
                 int kshift)
{
    const int K = 1 << kshift;
    const size_t i4 = ((size_t)blockIdx.x * blockDim.x + threadIdx.x) << 2;
    const size_t row = i4 >> kshift;
    const int col = (int)(i4 & (size_t)(K - 1));
    const float4 v = *(const float4*)&X[i4];
    __nv_bfloat16 h[4], l[4];
    h[0] = __float2bfloat16_rn(v.x); l[0] = __float2bfloat16_rn(v.x - __bfloat162float(h[0]));
    h[1] = __float2bfloat16_rn(v.y); l[1] = __float2bfloat16_rn(v.y - __bfloat162float(h[1]));
    h[2] = __float2bfloat16_rn(v.z); l[2] = __float2bfloat16_rn(v.z - __bfloat162float(h[2]));
    h[3] = __float2bfloat16_rn(v.w); l[3] = __float2bfloat16_rn(v.w - __bfloat162float(h[3]));
    __nv_bfloat16* out = O + row * (size_t)(3 * K);
    *(uint2*)&out[col]         = *(const uint2*)h;
    *(uint2*)&out[K + col]     = *(const uint2*)h;
    *(uint2*)&out[2 * K + col] = *(const uint2*)l;
}

__global__ void splitT3(const float* __restrict__ W, __nv_bfloat16* __restrict__ O,
                        int K, int N)
{
    __shared__ float t[32][33];
    const int n0 = blockIdx.x * 32, k0 = blockIdx.y * 32;
    const int tx = threadIdx.x, ty = threadIdx.y;
#pragma unroll
    for (int r = 0; r < 4; ++r)
        t[ty + 8 * r][tx] = W[(size_t)(k0 + ty + 8 * r) * N + n0 + tx];
    __syncthreads();
#pragma unroll
    for (int r = 0; r < 4; ++r) {
        const int n = n0 + ty + 8 * r, k = k0 + tx;
        const float v = t[tx][ty + 8 * r];
        const __nv_bfloat16 hi = __float2bfloat16_rn(v);
        const __nv_bfloat16 lo = __float2bfloat16_rn(v - __bfloat162float(hi));
        __nv_bfloat16* o = O + (size_t)n * 3 * K;
        o[k]         = hi;
        o[K + k]     = lo;
        o[2 * K + k] = hi;
    }
}

// fp32 -> (hi, lo) bf16, optional scale; flat over n elements (n % 1024 == 0)
__global__ __launch_bounds__(256)
void split2(const float* __restrict__ X, __nv_bfloat16* __restrict__ H,
            __nv_bfloat16* __restrict__ L, float scale)
{
    const size_t i4 = ((size_t)blockIdx.x * blockDim.x + threadIdx.x) << 2;
    const float4 v = *(const float4*)&X[i4];
    const float s[4] = {v.x * scale, v.y * scale, v.z * scale, v.w * scale};
    __nv_bfloat16 h[4], l[4];
#pragma unroll
    for (int j = 0; j < 4; ++j) {
        h[j] = __float2bfloat16_rn(s[j]);
        l[j] = __float2bfloat16_rn(s[j] - __bfloat162float(h[j]));
    }
    *(uint2*)&H[i4] = *(const uint2*)h;
    *(uint2*)&L[i4] = *(const uint2*)l;
}

// g_V [b][kv][h*64+d]  ->  vt_{h,l} [(b*16+h)*64+d][kv]   (per-head transpose)
__global__ void splitVT(const float* __restrict__ V,
                        __nv_bfloat16* __restrict__ TH,
                        __nv_bfloat16* __restrict__ TL)
{
    __shared__ float t[32][33];
    const int kv0 = blockIdx.x * 32;
    const int d0  = blockIdx.y * 32;
    const int bh  = blockIdx.z;
    const int b   = bh >> 4, h = bh & 15;
    const int tx  = threadIdx.x, ty = threadIdx.y;   // (32, 8)
#pragma unroll
    for (int r = 0; r < 4; ++r)
        t[ty + 8 * r][tx] =
            V[(size_t)(b * SLKV + kv0 + ty + 8 * r) * DMODEL + h * DHEAD + d0 + tx];
    __syncthreads();
#pragma unroll
    for (int r = 0; r < 4; ++r) {
        const float v = t[tx][ty + 8 * r];
        const __nv_bfloat16 hi = __float2bfloat16_rn(v);
        const size_t o = ((size_t)bh * DHEAD + d0 + ty + 8 * r) * SLKV + kv0 + tx;
        TH[o] = hi;
        TL[o] = __float2bfloat16_rn(v - __bfloat162float(hi));
    }
}

// ============================================================================
// Tensor-core flash attention v2: pre-split bf16 inputs, cp.async 3-stage ring,
// Q fragments hoisted to registers. Writes sp_a (3-segment) directly.
// ============================================================================
#define LDA   72
#define STG_E (4 * 64 * LDA)                       // Kh,Kl,Vth,Vtl per stage
#define ATTN_SMEM_BYTES ((2 * 128 * LDA + 3 * STG_E) * 2)

__global__ __launch_bounds__(256)
void attn_mma()
{
    extern __shared__ __nv_bfloat16 smb[];
    __nv_bfloat16* Qh  = smb;
    __nv_bfloat16* Ql  = Qh + 128 * LDA;
    __nv_bfloat16* stg = Ql + 128 * LDA;

    const int qb   = blockIdx.x;
    const int h    = blockIdx.y;
    const int b    = blockIdx.z;
    const int tid  = threadIdx.x;
    const int wid  = tid >> 5;
    const int lane = tid & 31;
    const int wm   = wid * 16;

    const __nv_bfloat16* Qhg = qs_h + ((size_t)b * SLQ + qb * 128) * DMODEL + h * DHEAD;
    const __nv_bfloat16* Qlg = qs_l + ((size_t)b * SLQ + qb * 128) * DMODEL + h * DHEAD;
    const __nv_bfloat16* Khg = ks_h + (size_t)b * SLKV * DMODEL + h * DHEAD;
    const __nv_bfloat16* Klg = ks_l + (size_t)b * SLKV * DMODEL + h * DHEAD;
    const __nv_bfloat16* Vhg = vt_h + (size_t)(b * NH + h) * DHEAD * SLKV;
    const __nv_bfloat16* Vlg = vt_l + (size_t)(b * NH + h) * DHEAD * SLKV;

#define LOAD_KV(s, kv0)                                                        \
    {                                                                          \
        __nv_bfloat16* S_ = stg + (s) * STG_E;                                 \
        _Pragma("unroll")                                                      \
        for (int c2 = 0; c2 < 2; ++c2) {                                       \
            const int c   = c2 * 256 + tid;                                    \
            const int row = c >> 3;                                            \
            const int off = (c & 7) << 3;                                      \
            cpa16(smem_u32(&S_[row * LDA + off]),                              \
                  Khg + (size_t)((kv0) + row) * DMODEL + off);                 \
            cpa16(smem_u32(&S_[64 * LDA + row * LDA + off]),                   \
                  Klg + (size_t)((kv0) + row) * DMODEL + off);                 \
            cpa16(smem_u32(&S_[2 * 64 * LDA + row * LDA + off]),               \
                  Vhg + (size_t)row * SLKV + (kv0) + off);                     \
            cpa16(smem_u32(&S_[3 * 64 * LDA + row * LDA + off]),               \
                  Vlg + (size_t)row * SLKV + (kv0) + off);                     \
        }                                                                      \
    }

    // prologue: Q (both buffers) + KV tile 0 in group 0, KV tile 1 in group 1
#pragma unroll
    for (int c2 = 0; c2 < 4; ++c2) {
        const int c   = c2 * 256 + tid;                 // 1024 chunks per buffer
        const int row = c >> 3;
        const int off = (c & 7) << 3;
        cpa16(smem_u32(&Qh[row * LDA + off]), Qhg + (size_t)row * DMODEL + off);
        cpa16(smem_u32(&Ql[row * LDA + off]), Qlg + (size_t)row * DMODEL + off);
    }
    LOAD_KV(0, 0);
    cpa_commit();
    LOAD_KV(1, 64);
    cpa_commit();

    cpa_wait1();          // group 0 (Q + tile 0) complete
    __syncthreads();

    // hoist Q fragments (reused for all 16 kv tiles)
    uint32_t qH[4][4], qL[4][4];
#pragma unroll
    for (int ks = 0; ks < 4; ++ks) {
        const int arow = wm + (lane & 15);
        const int acol = ks * 16 + (lane >> 4) * 8;
        ldmx4(qH[ks], smem_u32(&Qh[arow * LDA + acol]));
        ldmx4(qL[ks], smem_u32(&Ql[arow * LDA + acol]));
    }

    float Sa[8][4], Oa[8][4];
    float mrow[2] = {-3.0e38f, -3.0e38f};
    float lrow[2] = {0.0f, 0.0f};
#pragma unroll
    for (int t = 0; t < 8; ++t)
#pragma unroll
        for (int e = 0; e < 4; ++e) Oa[t][e] = 0.0f;

    for (int t = 0; t < 16; ++t) {
        if (t > 0) {
            cpa_wait1();       // tile t arrived (pending: {t, t+1} -> wait leaves t+1)
            __syncthreads();   // all warps done computing tile t-1
        }
        {
            const int tn = t + 2;
            if (tn < 16) LOAD_KV(tn % 3, tn * 64);
            cpa_commit();      // exactly one commit per iter (may be empty)
        }

        const __nv_bfloat16* Kh_  = stg + (t % 3) * STG_E;
        const __nv_bfloat16* Kl_  = Kh_ + 64 * LDA;
        const __nv_bfloat16* Vth_ = Kh_ + 2 * 64 * LDA;
        const __nv_bfloat16* Vtl_ = Kh_ + 3 * 64 * LDA;

        // ---- S = Q3 @ K3^T ----
#pragma unroll
        for (int u = 0; u < 8; ++u)
#pragma unroll
            for (int e = 0; e < 4; ++e) Sa[u][e] = 0.0f;

#pragma unroll
        for (int ks = 0; ks < 4; ++ks) {
#pragma unroll
            for (int np = 0; np < 4; ++np) {
                uint32_t bH[4], bL[4];
                const int brow = np * 16 + ((lane >> 4) & 1) * 8 + (lane & 7);
                const int bcol = ks * 16 + ((lane >> 3) & 1) * 8;
                ldmx4(bH, smem_u32(&Kh_[brow * LDA + bcol]));
                ldmx4(bL, smem_u32(&Kl_[brow * LDA + bcol]));
#pragma unroll
                for (int hf = 0; hf < 2; ++hf) {
                    float* c = Sa[np * 2 + hf];
                    mma16816(c, qH[ks], &bH[hf * 2]);
                    mma16816(c, qH[ks], &bL[hf * 2]);
                    mma16816(c, qL[ks], &bH[hf * 2]);
                }
            }
        }

        // ---- online softmax ----
        float mx0 = -3.0e38f, mx1 = -3.0e38f;
#pragma unroll
        for (int u = 0; u < 8; ++u) {
            mx0 = fmaxf(mx0, fmaxf(Sa[u][0], Sa[u][1]));
            mx1 = fmaxf(mx1, fmaxf(Sa[u][2], Sa[u][3]));
        }
        mx0 = fmaxf(mx0, __shfl_xor_sync(0xffffffffu, mx0, 1));
        mx0 = fmaxf(mx0, __shfl_xor_sync(0xffffffffu, mx0, 2));
        mx1 = fmaxf(mx1, __shfl_xor_sync(0xffffffffu, mx1, 1));
        mx1 = fmaxf(mx1, __shfl_xor_sync(0xffffffffu, mx1, 2));

        const float mn0 = fmaxf(mrow[0], mx0);
        const float mn1 = fmaxf(mrow[1], mx1);
        const float al0 = __expf(mrow[0] - mn0);
        const float al1 = __expf(mrow[1] - mn1);
        mrow[0] = mn0; mrow[1] = mn1;

        float sum0 = 0.0f, sum1 = 0.0f;
#pragma unroll
        for (int u = 0; u < 8; ++u) {
            Sa[u][0] = __expf(Sa[u][0] - mn0);
            Sa[u][1] = __expf(Sa[u][1] - mn0);
            Sa[u][2] = __expf(Sa[u][2] - mn1);
            Sa[u][3] = __expf(Sa[u][3] - mn1);
            sum0 += Sa[u][0] + Sa[u][1];
            sum1 += Sa[u][2] + Sa[u][3];
        }
        sum0 += __shfl_xor_sync(0xffffffffu, sum0, 1);
        sum0 += __shfl_xor_sync(0xffffffffu, sum0, 2);
        sum1 += __shfl_xor_sync(0xffffffffu, sum1, 1);
        sum1 += __shfl_xor_sync(0xffffffffu, sum1, 2);
        lrow[0] = lrow[0] * al0 + sum0;
        lrow[1] = lrow[1] * al1 + sum1;

#pragma unroll
        for (int u = 0; u < 8; ++u) {
            Oa[u][0] *= al0; Oa[u][1] *= al0;
            Oa[u][2] *= al1; Oa[u][3] *= al1;
        }

        // ---- O += P3 @ V3 ----
#pragma unroll
        for (int u = 0; u < 4; ++u) {
            uint32_t aH[4], aL[4];
            float lx, ly;
            aH[0] = pack_hi(Sa[2*u][0],   Sa[2*u][1],   lx, ly); aL[0] = pack2(lx, ly);
            aH[1] = pack_hi(Sa[2*u][2],   Sa[2*u][3],   lx, ly); aL[1] = pack2(lx, ly);
            aH[2] = pack_hi(Sa[2*u+1][0], Sa[2*u+1][1], lx, ly); aL[2] = pack2(lx, ly);
            aH[3] = pack_hi(Sa[2*u+1][2], Sa[2*u+1][3], lx, ly); aL[3] = pack2(lx, ly);
#pragma unroll
            for (int np = 0; np < 4; ++np) {
                uint32_t bH[4], bL[4];
                const int brow = np * 16 + ((lane >> 4) & 1) * 8 + (lane & 7);
                const int bcol = u * 16 + ((lane >> 3) & 1) * 8;
                ldmx4(bH, smem_u32(&Vth_[brow * LDA + bcol]));
                ldmx4(bL, smem_u32(&Vtl_[brow * LDA + bcol]));
#pragma unroll
                for (int hf = 0; hf < 2; ++hf) {
                    float* c = Oa[np * 2 + hf];
                    mma16816(c, aH, &bH[hf * 2]);
                    mma16816(c, aH, &bL[hf * 2]);
                    mma16816(c, aL, &bH[hf * 2]);
                }
            }
        }
    }
#undef LOAD_KV

    // ---- epilogue: normalize, write 3-segment sp_a directly ----
    const float inv0 = 1.0f / lrow[0];
    const float inv1 = 1.0f / lrow[1];
    const int qrow = qb * 128 + wm + (lane >> 2);
    __nv_bfloat16* out0 = sp_a + ((size_t)b * SLQ + qrow) * (3 * DMODEL) + h * DHEAD;
    __nv_bfloat16* out1 = out0 + (size_t)8 * (3 * DMODEL);
#pragma unroll
    for (int t = 0; t < 8; ++t) {
        const int d = t * 8 + (lane & 3) * 2;
        const float o0 = Oa[t][0] * inv0, o1 = Oa[t][1] * inv0;
        const float o2 = Oa[t][2] * inv1, o3 = Oa[t][3] * inv1;
        float lx, ly;
        uint32_t hi0 = pack_hi(o0, o1, lx, ly);
        uint32_t lo0 = pack2(lx, ly);
        *(uint32_t*)&out0[d]              = hi0;
        *(uint32_t*)&out0[DMODEL + d]     = hi0;
        *(uint32_t*)&out0[2 * DMODEL + d] = lo0;
        uint32_t hi1 = pack_hi(o2, o3, lx, ly);
        uint32_t lo1 = pack2(lx, ly);
        *(uint32_t*)&out1[d]              = hi1;
        *(uint32_t*)&out1[DMODEL + d]     = hi1;
        *(uint32_t*)&out1[2 * DMODEL + d] = lo1;
    }
}

// ============================================================================
// host side
// ============================================================================
extern "C" void kernel_launch(void* const* d_in, const int* in_sizes, int n_in,
                              void* d_out, int out_size)
{
    const float* q  = (const float*)d_in[0];
    const float* k  = (const float*)d_in[1];
    const float* v  = (const float*)d_in[2];
    const float* Wq = (const float*)d_in[3];
    const float* bq = (const float*)d_in[4];
    const float* Wk = (const float*)d_in[5];
    const float* bk = (const float*)d_in[6];
    const float* Wv = (const float*)d_in[7];
    const float* bv = (const float*)d_in[8];
    const float* Wo = (const float*)d_in[9];
    const float* bo = (const float*)d_in[10];
    float* out = (float*)d_out;

    float *gQ, *gK, *gV;
    cudaGetSymbolAddress((void**)&gQ, g_Q);
    cudaGetSymbolAddress((void**)&gK, g_K);
    cudaGetSymbolAddress((void**)&gV, g_V);
    __nv_bfloat16 *pq, *pk, *pv, *pa, *pwq, *pwk, *pwv, *pwo;
    __nv_bfloat16 *pqh, *pql, *pkh, *pkl, *pvh, *pvl;
    cudaGetSymbolAddress((void**)&pq,  sp_q);
    cudaGetSymbolAddress((void**)&pk,  sp_k);
    cudaGetSymbolAddress((void**)&pv,  sp_v);
    cudaGetSymbolAddress((void**)&pa,  sp_a);
    cudaGetSymbolAddress((void**)&pwq, tw_q);
    cudaGetSymbolAddress((void**)&pwk, tw_k);
    cudaGetSymbolAddress((void**)&pwv, tw_v);
    cudaGetSymbolAddress((void**)&pwo, tw_o);
    cudaGetSymbolAddress((void**)&pqh, qs_h);
    cudaGetSymbolAddress((void**)&pql, qs_l);
    cudaGetSymbolAddress((void**)&pkh, ks_h);
    cudaGetSymbolAddress((void**)&pkl, ks_l);
    cudaGetSymbolAddress((void**)&pvh, vt_h);
    cudaGetSymbolAddress((void**)&pvl, vt_l);

    cudaFuncSetAttribute(gemm_mma, cudaFuncAttributeMaxDynamicSharedMemorySize,
                         GEMM_SMEM_BYTES);
    cudaFuncSetAttribute(attn_mma, cudaFuncAttributeMaxDynamicSharedMemorySize,
                         ATTN_SMEM_BYTES);

    // gemm_mma at launches 6 AND 7 so ncu (-s 5, ±1) captures a GEMM
    split3_rows<<<(NB * SLQ * DMODEL) / 1024, 256>>>(q, pq, 10);                       // 1
    splitT3<<<dim3(DMODEL / 32, DMODEL / 32), dim3(32, 8)>>>(Wq, pwq, DMODEL, DMODEL); // 2
    split3_rows<<<(NB * SLKV * DIMG) / 1024, 256>>>(k, pk, 9);                         // 3
    splitT3<<<dim3(DMODEL / 32, DIMG / 32),   dim3(32, 8)>>>(Wk, pwk, DIMG, DMODEL);   // 4
    split3_rows<<<(NB * SLKV * DIMG) / 1024, 256>>>(v, pv, 9);                         // 5

    gemm_mma<<<dim3(DMODEL / GTN, NB * SLQ / 128), 256, GEMM_SMEM_BYTES>>>(            // 6
        pq, pwq, bq, gQ, 3 * DMODEL);
    gemm_mma<<<dim3(DMODEL / GTN, NB * SLKV / 128), 256, GEMM_SMEM_BYTES>>>(           // 7
        pk, pwk, bk, gK, 3 * DIMG);

    splitT3<<<dim3(DMODEL / 32, DIMG / 32),   dim3(32, 8)>>>(Wv, pwv, DIMG, DMODEL);   // 8
    splitT3<<<dim3(DMODEL / 32, DMODEL / 32), dim3(32, 8)>>>(Wo, pwo, DMODEL, DMODEL); // 9

    gemm_mma<<<dim3(DMODEL / GTN, NB * SLKV / 128), 256, GEMM_SMEM_BYTES>>>(           // 10
        pv, pwv, bv, gV, 3 * DIMG);

    // pre-split attention operands (once, not per q-block)
    split2<<<(NB * SLQ * DMODEL) / 1024, 256>>>(gQ, pqh, pql, 0.125f);                 // 11
    split2<<<(NB * SLKV * DMODEL) / 1024, 256>>>(gK, pkh, pkl, 1.0f);                  // 12
    splitVT<<<dim3(SLKV / 32, DHEAD / 32, NB * NH), dim3(32, 8)>>>(gV, pvh, pvl);      // 13

    attn_mma<<<dim3(SLQ / 128, NH, NB), 256, ATTN_SMEM_BYTES>>>();                     // 14

    gemm_mma<<<dim3(DMODEL / GTN, NB * SLQ / 128), 256, GEMM_SMEM_BYTES>>>(            // 15
        pa, pwo, bo, out, 3 * DMODEL);
}